// round 1
// baseline (speedup 1.0000x reference)
#include <cuda_runtime.h>
#include <cuda_bf16.h>
#include <math.h>

#define BB 4
#define CC 64
#define NN 9216   // 96*96

// Scratch (static device arrays; no allocation allowed)
__device__ float g_h[(size_t)BB * CC * NN];   // normalized input [B,C,N]
__device__ float g_q[(size_t)BB * NN * CC];   // [B,N,C]
__device__ float g_k[(size_t)BB * NN * CC];   // [B,N,C]
__device__ float g_v[(size_t)BB * NN * CC];   // [B,N,C]
__device__ float g_o[(size_t)BB * NN * CC];   // attention out [B,N,C]

// ---------------------------------------------------------------------------
// Kernel 1: instance norm. One block per (b,c) pair (256 blocks), 256 threads.
// ---------------------------------------------------------------------------
__global__ __launch_bounds__(256) void instnorm_kernel(const float* __restrict__ x) {
    int bc = blockIdx.x;                      // 0..255 == b*C + c
    const float4* xp = (const float4*)(x + (size_t)bc * NN);
    float4* hp = (float4*)(g_h + (size_t)bc * NN);
    int tid = threadIdx.x;

    float s = 0.f, ss = 0.f;
    for (int i = tid; i < NN / 4; i += 256) {
        float4 v = xp[i];
        s  += v.x + v.y + v.z + v.w;
        ss += v.x * v.x + v.y * v.y + v.z * v.z + v.w * v.w;
    }
    __shared__ float rs[256], rss[256];
    rs[tid] = s; rss[tid] = ss;
    __syncthreads();
    for (int off = 128; off > 0; off >>= 1) {
        if (tid < off) { rs[tid] += rs[tid + off]; rss[tid] += rss[tid + off]; }
        __syncthreads();
    }
    __shared__ float smean, srstd;
    if (tid == 0) {
        float mean = rs[0] * (1.0f / NN);
        float var  = rss[0] * (1.0f / NN) - mean * mean;
        smean = mean;
        srstd = rsqrtf(var + 1e-5f);
    }
    __syncthreads();
    float mean = smean, rstd = srstd;
    for (int i = tid; i < NN / 4; i += 256) {
        float4 v = xp[i];
        v.x = (v.x - mean) * rstd;
        v.y = (v.y - mean) * rstd;
        v.z = (v.z - mean) * rstd;
        v.w = (v.w - mean) * rstd;
        hp[i] = v;
    }
}

// ---------------------------------------------------------------------------
// Kernel 2: fused Q/K/V 1x1 convs. One block per 64 spatial positions.
// Output layout [B,N,64] (row per position) for contiguous attention loads.
// ---------------------------------------------------------------------------
__global__ __launch_bounds__(256) void qkv_kernel(
    const float* __restrict__ wq, const float* __restrict__ bq,
    const float* __restrict__ wk, const float* __restrict__ bk,
    const float* __restrict__ wv, const float* __restrict__ bv)
{
    __shared__ float hs[64 * 65];     // [c][p] padded
    __shared__ float outs[64 * 65];   // staging for coalesced writes

    int tile = blockIdx.x;
    int b    = tile / (NN / 64);
    int n0   = (tile % (NN / 64)) * 64;
    int tid  = threadIdx.x;
    int p    = tid & 63;    // position within tile (lane-contiguous)
    int og   = tid >> 6;    // output-channel group 0..3

    // Stage h tile: coalesced global reads along p
    for (int idx = tid; idx < 64 * 64; idx += 256) {
        int c = idx >> 6, pp = idx & 63;
        hs[c * 65 + pp] = g_h[((size_t)b * CC + c) * NN + n0 + pp];
    }
    __syncthreads();

    float aq[16], ak[16], av[16];
#pragma unroll
    for (int i = 0; i < 16; i++) {
        int o = og * 16 + i;
        aq[i] = bq[o]; ak[i] = bk[o]; av[i] = bv[o];
    }

    for (int c4 = 0; c4 < 64; c4 += 4) {
        float h0 = hs[(c4 + 0) * 65 + p];
        float h1 = hs[(c4 + 1) * 65 + p];
        float h2 = hs[(c4 + 2) * 65 + p];
        float h3 = hs[(c4 + 3) * 65 + p];
#pragma unroll
        for (int i = 0; i < 16; i++) {
            int o = og * 16 + i;   // same o across warp -> broadcast weight loads
            float4 w;
            w = *(const float4*)(wq + o * 64 + c4);
            aq[i] += w.x * h0 + w.y * h1 + w.z * h2 + w.w * h3;
            w = *(const float4*)(wk + o * 64 + c4);
            ak[i] += w.x * h0 + w.y * h1 + w.z * h2 + w.w * h3;
            w = *(const float4*)(wv + o * 64 + c4);
            av[i] += w.x * h0 + w.y * h1 + w.z * h2 + w.w * h3;
        }
    }

    // Flush each matrix via smem so global writes are coalesced
    float* dsts[3] = {
        g_q + ((size_t)b * NN + n0) * 64,
        g_k + ((size_t)b * NN + n0) * 64,
        g_v + ((size_t)b * NN + n0) * 64
    };
    for (int m = 0; m < 3; m++) {
        const float* acc = (m == 0) ? aq : (m == 1) ? ak : av;
        __syncthreads();
#pragma unroll
        for (int i = 0; i < 16; i++) outs[p * 65 + og * 16 + i] = acc[i];
        __syncthreads();
        float* dst = dsts[m];
        for (int idx = tid; idx < 64 * 64; idx += 256) {
            int pp = idx >> 6, oo = idx & 63;
            dst[pp * 64 + oo] = outs[pp * 65 + oo];
        }
    }
}

// ---------------------------------------------------------------------------
// Kernel 3: flash-style attention. 1 query per thread, 128 threads/block.
// K/V tiles of 64 keys in smem; online softmax in 16-key register chunks.
// ---------------------------------------------------------------------------
__global__ __launch_bounds__(128) void attn_kernel() {
    __shared__ float4 Ksh[64 * 16];   // 64 keys x 64 dims
    __shared__ float4 Vsh[64 * 16];

    int b  = blockIdx.y;
    int qi = blockIdx.x * 128 + threadIdx.x;

    const float4* qp = (const float4*)(g_q + ((size_t)b * NN + qi) * 64);
    float4 q4[16], a4[16];
#pragma unroll
    for (int i = 0; i < 16; i++) {
        q4[i] = qp[i];
        a4[i] = make_float4(0.f, 0.f, 0.f, 0.f);
    }
    float m = -1e30f, l = 0.f;

    for (int kt = 0; kt < NN; kt += 64) {
        __syncthreads();
        const float4* ks = (const float4*)(g_k + ((size_t)b * NN + kt) * 64);
        const float4* vs = (const float4*)(g_v + ((size_t)b * NN + kt) * 64);
        for (int idx = threadIdx.x; idx < 1024; idx += 128) {
            Ksh[idx] = ks[idx];
            Vsh[idx] = vs[idx];
        }
        __syncthreads();

        for (int j0 = 0; j0 < 64; j0 += 16) {
            float s[16];
            float cmax = -1e30f;
#pragma unroll
            for (int jj = 0; jj < 16; jj++) {
                const float4* kr = &Ksh[(j0 + jj) * 16];
                float acc = 0.f;
#pragma unroll
                for (int i = 0; i < 16; i++) {
                    float4 kv = kr[i];   // broadcast across warp
                    acc += q4[i].x * kv.x + q4[i].y * kv.y
                         + q4[i].z * kv.z + q4[i].w * kv.w;
                }
                s[jj] = acc * 0.125f;    // C^-0.5 = 1/8
                cmax = fmaxf(cmax, s[jj]);
            }
            float mnew = fmaxf(m, cmax);
            float corr = __expf(m - mnew);
            m = mnew;
            l *= corr;
#pragma unroll
            for (int i = 0; i < 16; i++) {
                a4[i].x *= corr; a4[i].y *= corr; a4[i].z *= corr; a4[i].w *= corr;
            }
#pragma unroll
            for (int jj = 0; jj < 16; jj++) {
                float pe = __expf(s[jj] - mnew);
                l += pe;
                const float4* vr = &Vsh[(j0 + jj) * 16];
#pragma unroll
                for (int i = 0; i < 16; i++) {
                    float4 vv = vr[i];   // broadcast across warp
                    a4[i].x += pe * vv.x; a4[i].y += pe * vv.y;
                    a4[i].z += pe * vv.z; a4[i].w += pe * vv.w;
                }
            }
        }
    }

    float inv = 1.0f / l;
    float4* op = (float4*)(g_o + ((size_t)b * NN + qi) * 64);
#pragma unroll
    for (int i = 0; i < 16; i++) {
        float4 v = a4[i];
        v.x *= inv; v.y *= inv; v.z *= inv; v.w *= inv;
        op[i] = v;
    }
}

// ---------------------------------------------------------------------------
// Kernel 4: output 1x1 conv + residual. One block per 64 positions.
// ---------------------------------------------------------------------------
__global__ __launch_bounds__(256) void out_kernel(
    const float* __restrict__ x,
    const float* __restrict__ wo, const float* __restrict__ bo,
    float* __restrict__ out)
{
    __shared__ float osh[64 * 65];    // [p][ci] padded

    int tile = blockIdx.x;
    int b    = tile / (NN / 64);
    int n0   = (tile % (NN / 64)) * 64;
    int tid  = threadIdx.x;
    int p    = tid & 63;   // position (lane-contiguous -> coalesced final write)
    int cg   = tid >> 6;   // channel group 0..3

    // Stage attention-output tile: coalesced reads (ci inner)
    for (int idx = tid; idx < 64 * 64; idx += 256) {
        int pp = idx >> 6, oo = idx & 63;
        osh[pp * 65 + oo] = g_o[((size_t)b * NN + n0 + pp) * 64 + oo];
    }
    __syncthreads();

    float acc[16];
#pragma unroll
    for (int i = 0; i < 16; i++) acc[i] = bo[cg * 16 + i];

    for (int c4 = 0; c4 < 64; c4 += 4) {
        float o0 = osh[p * 65 + c4 + 0];
        float o1 = osh[p * 65 + c4 + 1];
        float o2 = osh[p * 65 + c4 + 2];
        float o3 = osh[p * 65 + c4 + 3];
#pragma unroll
        for (int i = 0; i < 16; i++) {
            int co = cg * 16 + i;   // same co across warp -> broadcast weights
            float4 w = *(const float4*)(wo + co * 64 + c4);
            acc[i] += w.x * o0 + w.y * o1 + w.z * o2 + w.w * o3;
        }
    }
#pragma unroll
    for (int i = 0; i < 16; i++) {
        int co = cg * 16 + i;
        size_t oidx = ((size_t)b * CC + co) * NN + n0 + p;
        out[oidx] = x[oidx] + acc[i];   // coalesced (p lane-contiguous)
    }
}

// ---------------------------------------------------------------------------
extern "C" void kernel_launch(void* const* d_in, const int* in_sizes, int n_in,
                              void* d_out, int out_size)
{
    const float* x  = (const float*)d_in[0];
    const float* wq = (const float*)d_in[1];
    const float* bq = (const float*)d_in[2];
    const float* wk = (const float*)d_in[3];
    const float* bk = (const float*)d_in[4];
    const float* wv = (const float*)d_in[5];
    const float* bv = (const float*)d_in[6];
    const float* wo = (const float*)d_in[7];
    const float* bo = (const float*)d_in[8];
    float* out = (float*)d_out;

    instnorm_kernel<<<BB * CC, 256>>>(x);
    qkv_kernel<<<BB * (NN / 64), 256>>>(wq, bq, wk, bk, wv, bv);
    attn_kernel<<<dim3(NN / 128, BB), 128>>>();
    out_kernel<<<BB * (NN / 64), 256>>>(x, wo, bo, out);
}

// round 2
// speedup vs baseline: 7.4596x; 7.4596x over previous
#include <cuda_runtime.h>
#include <cuda_fp16.h>
#include <cuda_bf16.h>
#include <math.h>

#define BB 4
#define CC 64
#define NN 9216   // 96*96
#define NT (NN/64)    // 144 key tiles
#define QBLK 128      // queries per attention block

// Scratch (static device arrays; no allocation allowed)
__device__ float g_h[(size_t)BB * CC * NN];   // normalized input [B,C,N]
__device__ float g_q[(size_t)BB * NN * CC];   // Q packed in tf32 A-fragment order
__device__ float g_k[(size_t)BB * NN * CC];   // K packed in tf32 B-fragment order
__device__ float g_v[(size_t)BB * NN * CC];   // V packed fp16 B-fragment order (half the space used)
__device__ float g_o[(size_t)BB * NN * CC];   // attention out [B,N,64]

// ---------------------------------------------------------------------------
// helpers
// ---------------------------------------------------------------------------
static __device__ __forceinline__ unsigned smem_u32(const void* p) {
    return (unsigned)__cvta_generic_to_shared(p);
}
static __device__ __forceinline__ void cp_async16(unsigned dst, const void* src) {
    asm volatile("cp.async.cg.shared.global [%0], [%1], 16;" :: "r"(dst), "l"(src) : "memory");
}
static __device__ __forceinline__ void cp_commit() {
    asm volatile("cp.async.commit_group;" ::: "memory");
}
static __device__ __forceinline__ float tf32r(float x) {
    unsigned y;
    asm("cvt.rna.tf32.f32 %0, %1;" : "=r"(y) : "f"(x));
    return __uint_as_float(y);
}
static __device__ __forceinline__ unsigned pack_h2(float a, float b) {
    __half2 h = __floats2half2_rn(a, b);
    return *reinterpret_cast<unsigned*>(&h);
}
static __device__ __forceinline__ void mma_tf32(float* d, const unsigned* a, float2 b) {
    asm volatile(
        "mma.sync.aligned.m16n8k8.row.col.f32.tf32.tf32.f32 "
        "{%0,%1,%2,%3},{%4,%5,%6,%7},{%8,%9},{%0,%1,%2,%3};"
        : "+f"(d[0]), "+f"(d[1]), "+f"(d[2]), "+f"(d[3])
        : "r"(a[0]), "r"(a[1]), "r"(a[2]), "r"(a[3]),
          "r"(__float_as_uint(b.x)), "r"(__float_as_uint(b.y)));
}
static __device__ __forceinline__ void mma_f16(float* d, const unsigned* a, uint2 b) {
    asm volatile(
        "mma.sync.aligned.m16n8k16.row.col.f32.f16.f16.f32 "
        "{%0,%1,%2,%3},{%4,%5,%6,%7},{%8,%9},{%0,%1,%2,%3};"
        : "+f"(d[0]), "+f"(d[1]), "+f"(d[2]), "+f"(d[3])
        : "r"(a[0]), "r"(a[1]), "r"(a[2]), "r"(a[3]),
          "r"(b.x), "r"(b.y));
}

// ---------------------------------------------------------------------------
// Kernel 1: instance norm. One block per (b,c) pair (256 blocks), 256 threads.
// ---------------------------------------------------------------------------
__global__ __launch_bounds__(256) void instnorm_kernel(const float* __restrict__ x) {
    int bc = blockIdx.x;
    const float4* xp = (const float4*)(x + (size_t)bc * NN);
    float4* hp = (float4*)(g_h + (size_t)bc * NN);
    int tid = threadIdx.x;

    float s = 0.f, ss = 0.f;
    for (int i = tid; i < NN / 4; i += 256) {
        float4 v = xp[i];
        s  += v.x + v.y + v.z + v.w;
        ss += v.x * v.x + v.y * v.y + v.z * v.z + v.w * v.w;
    }
    __shared__ float rs[256], rss[256];
    rs[tid] = s; rss[tid] = ss;
    __syncthreads();
    for (int off = 128; off > 0; off >>= 1) {
        if (tid < off) { rs[tid] += rs[tid + off]; rss[tid] += rss[tid + off]; }
        __syncthreads();
    }
    __shared__ float smean, srstd;
    if (tid == 0) {
        float mean = rs[0] * (1.0f / NN);
        float var  = rss[0] * (1.0f / NN) - mean * mean;
        smean = mean;
        srstd = rsqrtf(var + 1e-5f);
    }
    __syncthreads();
    float mean = smean, rstd = srstd;
    for (int i = tid; i < NN / 4; i += 256) {
        float4 v = xp[i];
        v.x = (v.x - mean) * rstd;
        v.y = (v.y - mean) * rstd;
        v.z = (v.z - mean) * rstd;
        v.w = (v.w - mean) * rstd;
        hp[i] = v;
    }
}

// ---------------------------------------------------------------------------
// Kernel 2: fused Q/K/V 1x1 convs + fragment packing.
// Q: tf32 A-frag (m16n8k8) order, pre-scaled by C^-0.5 = 1/8.
// K: tf32 B-frag (m16n8k8) order.
// V: fp16 B-frag (m16n8k16) order.
// ---------------------------------------------------------------------------
__global__ __launch_bounds__(256) void qkv_kernel(
    const float* __restrict__ wq, const float* __restrict__ bq,
    const float* __restrict__ wk, const float* __restrict__ bk,
    const float* __restrict__ wv, const float* __restrict__ bv)
{
    __shared__ float hs[64 * 65];     // [c][p] padded
    __shared__ float outs[64 * 65];   // staging [p][o] padded

    int tile = blockIdx.x;
    int b    = tile / (NN / 64);
    int n0   = (tile % (NN / 64)) * 64;
    int tid  = threadIdx.x;
    int p    = tid & 63;
    int og   = tid >> 6;

    for (int idx = tid; idx < 64 * 64; idx += 256) {
        int c = idx >> 6, pp = idx & 63;
        hs[c * 65 + pp] = g_h[((size_t)b * CC + c) * NN + n0 + pp];
    }
    __syncthreads();

    float aq[16], ak[16], av[16];
#pragma unroll
    for (int i = 0; i < 16; i++) {
        int o = og * 16 + i;
        aq[i] = bq[o]; ak[i] = bk[o]; av[i] = bv[o];
    }

    for (int c4 = 0; c4 < 64; c4 += 4) {
        float h0 = hs[(c4 + 0) * 65 + p];
        float h1 = hs[(c4 + 1) * 65 + p];
        float h2 = hs[(c4 + 2) * 65 + p];
        float h3 = hs[(c4 + 3) * 65 + p];
#pragma unroll
        for (int i = 0; i < 16; i++) {
            int o = og * 16 + i;
            float4 w;
            w = *(const float4*)(wq + o * 64 + c4);
            aq[i] += w.x * h0 + w.y * h1 + w.z * h2 + w.w * h3;
            w = *(const float4*)(wk + o * 64 + c4);
            ak[i] += w.x * h0 + w.y * h1 + w.z * h2 + w.w * h3;
            w = *(const float4*)(wv + o * 64 + c4);
            av[i] += w.x * h0 + w.y * h1 + w.z * h2 + w.w * h3;
        }
    }

    size_t tbase = (size_t)b * NN * 64 + (size_t)n0 * 64;

    // ---- Q: stage (scaled), pack as tf32 A-fragments ----
    __syncthreads();
#pragma unroll
    for (int i = 0; i < 16; i++) outs[p * 65 + og * 16 + i] = aq[i] * 0.125f;
    __syncthreads();
    {
        float* qdst = g_q + tbase;
        for (int idx = tid; idx < 4096; idx += 256) {
            int qb = idx >> 10;
            int kk = (idx >> 7) & 7;
            int ln = (idx >> 2) & 31;
            int rg = idx & 3;
            int r = (ln >> 2) | ((rg & 1) << 3);
            int c = (ln & 3) | ((rg & 2) << 1);
            qdst[idx] = tf32r(outs[(qb * 16 + r) * 65 + kk * 8 + c]);
        }
    }

    // ---- K: stage, pack as tf32 B-fragments ----
    __syncthreads();
#pragma unroll
    for (int i = 0; i < 16; i++) outs[p * 65 + og * 16 + i] = ak[i];
    __syncthreads();
    {
        float* kdst = g_k + tbase;
        for (int idx = tid; idx < 4096; idx += 256) {
            int nb = idx >> 9;
            int kk = (idx >> 6) & 7;
            int ln = (idx >> 1) & 31;
            int rg = idx & 1;
            int key = nb * 8 + (ln >> 2);
            int d = kk * 8 + ((ln & 3) | (rg << 2));
            kdst[idx] = tf32r(outs[key * 65 + d]);
        }
    }

    // ---- V: stage, pack as fp16 B-fragments ----
    __syncthreads();
#pragma unroll
    for (int i = 0; i < 16; i++) outs[p * 65 + og * 16 + i] = av[i];
    __syncthreads();
    {
        unsigned* vdst = (unsigned*)((__half*)g_v + tbase);
        for (int idx = tid; idx < 2048; idx += 256) {
            int kb = idx >> 9;
            int db = (idx >> 6) & 7;
            int ln = (idx >> 1) & 31;
            int rg = idx & 1;
            int kr0 = ((ln & 3) << 1) | (rg << 3);
            int key0 = kb * 16 + kr0;
            int d = db * 8 + (ln >> 2);
            vdst[idx] = pack_h2(outs[key0 * 65 + d], outs[(key0 + 1) * 65 + d]);
        }
    }
}

// ---------------------------------------------------------------------------
// Kernel 3: tensor-core flash attention.
// 128 threads (4 warps), each warp owns 32 queries (two m16 tiles).
// 64-key tiles double-buffered via cp.async. QK: tf32 mma. PV: fp16 mma.
// ---------------------------------------------------------------------------
__global__ void __launch_bounds__(128, 2) attn_kernel() {
    __shared__ float4 KV[2][1536];   // per buf: K = 1024 float4 (16KB), V = 512 float4 (8KB)

    int b    = blockIdx.y;
    int w    = threadIdx.x >> 5;
    int lane = threadIdx.x & 31;

    // ---- load Q fragments (held in registers for whole kernel) ----
    unsigned qa[2][8][4];
    {
        const float4* qbase = (const float4*)g_q + (size_t)b * NN * 16;
        int qblk0 = blockIdx.x * 8 + w * 2;
#pragma unroll
        for (int t = 0; t < 2; t++)
#pragma unroll
            for (int kk = 0; kk < 8; kk++) {
                float4 v = qbase[((qblk0 + t) * 8 + kk) * 32 + lane];
                qa[t][kk][0] = __float_as_uint(v.x);
                qa[t][kk][1] = __float_as_uint(v.y);
                qa[t][kk][2] = __float_as_uint(v.z);
                qa[t][kk][3] = __float_as_uint(v.w);
            }
    }

    float O[2][8][4];
    float S[2][8][4];
    float mrow[2][2], lrow[2][2];
#pragma unroll
    for (int t = 0; t < 2; t++) {
#pragma unroll
        for (int db = 0; db < 8; db++) {
            O[t][db][0] = 0.f; O[t][db][1] = 0.f; O[t][db][2] = 0.f; O[t][db][3] = 0.f;
        }
        mrow[t][0] = -1e30f; mrow[t][1] = -1e30f;
        lrow[t][0] = 0.f;    lrow[t][1] = 0.f;
    }

    const float4* ksrc = (const float4*)g_k + (size_t)b * NN * 16;
    const float4* vsrc = (const float4*)g_v + (size_t)b * NN * 8;   // fp16 tile = 512 float4

    // prologue: issue tile 0
    {
        unsigned sb = smem_u32(&KV[0][0]);
        for (int i = threadIdx.x; i < 1536; i += 128) {
            const float4* src = (i < 1024) ? (ksrc + i) : (vsrc + (i - 1024));
            cp_async16(sb + i * 16, src);
        }
        cp_commit();
    }

    for (int tl = 0; tl < NT; tl++) {
        int buf = tl & 1;
        if (tl + 1 < NT) {
            unsigned sb = smem_u32(&KV[buf ^ 1][0]);
            const float4* kb = ksrc + (size_t)(tl + 1) * 1024;
            const float4* vb = vsrc + (size_t)(tl + 1) * 512;
            for (int i = threadIdx.x; i < 1536; i += 128) {
                const float4* src = (i < 1024) ? (kb + i) : (vb + (i - 1024));
                cp_async16(sb + i * 16, src);
            }
            cp_commit();
            asm volatile("cp.async.wait_group 1;" ::: "memory");
        } else {
            asm volatile("cp.async.wait_group 0;" ::: "memory");
        }
        __syncthreads();

        const float2* Kf = (const float2*)&KV[buf][0];
        const uint2*  Vf = (const uint2*)&KV[buf][1024];

        // ---- S = Q * K^T (tf32) ----
#pragma unroll
        for (int nb = 0; nb < 8; nb++) {
            float2 kf[8];
#pragma unroll
            for (int kk = 0; kk < 8; kk++) kf[kk] = Kf[(nb * 8 + kk) * 32 + lane];
#pragma unroll
            for (int t = 0; t < 2; t++) {
                S[t][nb][0] = 0.f; S[t][nb][1] = 0.f; S[t][nb][2] = 0.f; S[t][nb][3] = 0.f;
#pragma unroll
                for (int kk = 0; kk < 8; kk++) mma_tf32(S[t][nb], qa[t][kk], kf[kk]);
            }
        }

        // ---- online softmax ----
#pragma unroll
        for (int t = 0; t < 2; t++)
#pragma unroll
            for (int h = 0; h < 2; h++) {
                float mx = -1e30f;
#pragma unroll
                for (int nb = 0; nb < 8; nb++)
                    mx = fmaxf(mx, fmaxf(S[t][nb][2 * h], S[t][nb][2 * h + 1]));
                mx = fmaxf(mx, __shfl_xor_sync(0xffffffffu, mx, 1));
                mx = fmaxf(mx, __shfl_xor_sync(0xffffffffu, mx, 2));
                float mo = mrow[t][h];
                float mn = fmaxf(mo, mx);
                mrow[t][h] = mn;
                float corr = __expf(mo - mn);
                float lacc = lrow[t][h] * corr;
#pragma unroll
                for (int db = 0; db < 8; db++) {
                    O[t][db][2 * h]     *= corr;
                    O[t][db][2 * h + 1] *= corr;
                }
                float ps = 0.f;
#pragma unroll
                for (int nb = 0; nb < 8; nb++) {
                    float e0 = __expf(S[t][nb][2 * h]     - mn);
                    float e1 = __expf(S[t][nb][2 * h + 1] - mn);
                    S[t][nb][2 * h]     = e0;
                    S[t][nb][2 * h + 1] = e1;
                    ps += e0 + e1;
                }
                lrow[t][h] = lacc + ps;
            }

        // ---- O += P * V (fp16) ----
#pragma unroll
        for (int ks = 0; ks < 4; ks++) {
            unsigned pa[2][4];
#pragma unroll
            for (int t = 0; t < 2; t++) {
                pa[t][0] = pack_h2(S[t][2 * ks][0],     S[t][2 * ks][1]);
                pa[t][1] = pack_h2(S[t][2 * ks][2],     S[t][2 * ks][3]);
                pa[t][2] = pack_h2(S[t][2 * ks + 1][0], S[t][2 * ks + 1][1]);
                pa[t][3] = pack_h2(S[t][2 * ks + 1][2], S[t][2 * ks + 1][3]);
            }
#pragma unroll
            for (int db = 0; db < 8; db++) {
                uint2 vb = Vf[(ks * 8 + db) * 32 + lane];
                mma_f16(O[0][db], pa[0], vb);
                mma_f16(O[1][db], pa[1], vb);
            }
        }
        __syncthreads();
    }

    // ---- finalize: normalize and store [B,N,64] ----
    float linv[2][2];
#pragma unroll
    for (int t = 0; t < 2; t++)
#pragma unroll
        for (int h = 0; h < 2; h++) {
            float l = lrow[t][h];
            l += __shfl_xor_sync(0xffffffffu, l, 1);
            l += __shfl_xor_sync(0xffffffffu, l, 2);
            linv[t][h] = 1.0f / l;
        }

    int q0 = blockIdx.x * QBLK + w * 32 + (lane >> 2);
#pragma unroll
    for (int t = 0; t < 2; t++)
#pragma unroll
        for (int h = 0; h < 2; h++) {
            int q = q0 + t * 16 + h * 8;
            float iv = linv[t][h];
            float* op = g_o + ((size_t)b * NN + q) * 64 + (lane & 3) * 2;
#pragma unroll
            for (int db = 0; db < 8; db++) {
                float2 v = make_float2(O[t][db][2 * h] * iv, O[t][db][2 * h + 1] * iv);
                *(float2*)(op + db * 8) = v;
            }
        }
}

// ---------------------------------------------------------------------------
// Kernel 4: output 1x1 conv + residual. One block per 64 positions.
// ---------------------------------------------------------------------------
__global__ __launch_bounds__(256) void out_kernel(
    const float* __restrict__ x,
    const float* __restrict__ wo, const float* __restrict__ bo,
    float* __restrict__ out)
{
    __shared__ float osh[64 * 65];

    int tile = blockIdx.x;
    int b    = tile / (NN / 64);
    int n0   = (tile % (NN / 64)) * 64;
    int tid  = threadIdx.x;
    int p    = tid & 63;
    int cg   = tid >> 6;

    for (int idx = tid; idx < 64 * 64; idx += 256) {
        int pp = idx >> 6, oo = idx & 63;
        osh[pp * 65 + oo] = g_o[((size_t)b * NN + n0 + pp) * 64 + oo];
    }
    __syncthreads();

    float acc[16];
#pragma unroll
    for (int i = 0; i < 16; i++) acc[i] = bo[cg * 16 + i];

    for (int c4 = 0; c4 < 64; c4 += 4) {
        float o0 = osh[p * 65 + c4 + 0];
        float o1 = osh[p * 65 + c4 + 1];
        float o2 = osh[p * 65 + c4 + 2];
        float o3 = osh[p * 65 + c4 + 3];
#pragma unroll
        for (int i = 0; i < 16; i++) {
            int co = cg * 16 + i;
            float4 w = *(const float4*)(wo + co * 64 + c4);
            acc[i] += w.x * o0 + w.y * o1 + w.z * o2 + w.w * o3;
        }
    }
#pragma unroll
    for (int i = 0; i < 16; i++) {
        int co = cg * 16 + i;
        size_t oidx = ((size_t)b * CC + co) * NN + n0 + p;
        out[oidx] = x[oidx] + acc[i];
    }
}

// ---------------------------------------------------------------------------
extern "C" void kernel_launch(void* const* d_in, const int* in_sizes, int n_in,
                              void* d_out, int out_size)
{
    const float* x  = (const float*)d_in[0];
    const float* wq = (const float*)d_in[1];
    const float* bq = (const float*)d_in[2];
    const float* wk = (const float*)d_in[3];
    const float* bk = (const float*)d_in[4];
    const float* wv = (const float*)d_in[5];
    const float* bv = (const float*)d_in[6];
    const float* wo = (const float*)d_in[7];
    const float* bo = (const float*)d_in[8];
    float* out = (float*)d_out;

    instnorm_kernel<<<BB * CC, 256>>>(x);
    qkv_kernel<<<BB * (NN / 64), 256>>>(wq, bq, wk, bk, wv, bv);
    attn_kernel<<<dim3(NN / QBLK, BB), 128>>>();
    out_kernel<<<BB * (NN / 64), 256>>>(x, wo, bo, out);
}

// round 3
// speedup vs baseline: 9.4665x; 1.2690x over previous
#include <cuda_runtime.h>
#include <cuda_fp16.h>
#include <cuda_bf16.h>
#include <math.h>

#define BB 4
#define CC 64
#define NN 9216     // 96*96
#define NT (NN/64)  // 144 key tiles of 64
#define QBLK 256    // queries per attention block (8 warps x 32)

// Scratch (static device arrays; no allocation allowed)
__device__ float g_stats[BB * CC * 2];        // mean, rstd per (b,c)
__device__ float g_q[(size_t)BB * NN * CC / 2];  // fp16 A-frag packed (m16n8k16)
__device__ float g_k[(size_t)BB * NN * CC / 2];  // fp16 B-frag packed
__device__ float g_v[(size_t)BB * NN * CC / 2];  // fp16 B-frag packed
__device__ float g_o[(size_t)BB * NN * CC];      // attention out [B,N,64] fp32

// ---------------------------------------------------------------------------
// helpers
// ---------------------------------------------------------------------------
static __device__ __forceinline__ unsigned smem_u32(const void* p) {
    return (unsigned)__cvta_generic_to_shared(p);
}
static __device__ __forceinline__ void cp_async16(unsigned dst, const void* src) {
    asm volatile("cp.async.cg.shared.global [%0], [%1], 16;" :: "r"(dst), "l"(src) : "memory");
}
static __device__ __forceinline__ void cp_commit() {
    asm volatile("cp.async.commit_group;" ::: "memory");
}
static __device__ __forceinline__ unsigned pack_h2(float a, float b) {
    __half2 h = __floats2half2_rn(a, b);
    return *reinterpret_cast<unsigned*>(&h);
}
static __device__ __forceinline__ unsigned ex2_h2(unsigned h) {
    unsigned r;
    asm("ex2.approx.f16x2 %0, %1;" : "=r"(r) : "r"(h));
    return r;
}
static __device__ __forceinline__ void mma_f16(float* d, const unsigned* a, uint2 b) {
    asm volatile(
        "mma.sync.aligned.m16n8k16.row.col.f32.f16.f16.f32 "
        "{%0,%1,%2,%3},{%4,%5,%6,%7},{%8,%9},{%0,%1,%2,%3};"
        : "+f"(d[0]), "+f"(d[1]), "+f"(d[2]), "+f"(d[3])
        : "r"(a[0]), "r"(a[1]), "r"(a[2]), "r"(a[3]),
          "r"(b.x), "r"(b.y));
}

// ---------------------------------------------------------------------------
// Kernel 1: instance-norm statistics only. One block per (b,c).
// ---------------------------------------------------------------------------
__global__ __launch_bounds__(256) void stats_kernel(const float* __restrict__ x) {
    int bc = blockIdx.x;
    const float4* xp = (const float4*)(x + (size_t)bc * NN);
    int tid = threadIdx.x;

    float s = 0.f, ss = 0.f;
    for (int i = tid; i < NN / 4; i += 256) {
        float4 v = xp[i];
        s  += v.x + v.y + v.z + v.w;
        ss += v.x * v.x + v.y * v.y + v.z * v.z + v.w * v.w;
    }
    __shared__ float rs[256], rss[256];
    rs[tid] = s; rss[tid] = ss;
    __syncthreads();
    for (int off = 128; off > 0; off >>= 1) {
        if (tid < off) { rs[tid] += rs[tid + off]; rss[tid] += rss[tid + off]; }
        __syncthreads();
    }
    if (tid == 0) {
        float mean = rs[0] * (1.0f / NN);
        float var  = rss[0] * (1.0f / NN) - mean * mean;
        g_stats[bc * 2]     = mean;
        g_stats[bc * 2 + 1] = rsqrtf(var + 1e-5f);
    }
}

// ---------------------------------------------------------------------------
// Kernel 2: fused norm + Q/K/V 1x1 convs + fp16 fragment packing.
// Q: fp16 A-frag (m16n8k16), pre-scaled by C^-0.5 * log2(e).
// K: fp16 B-frag (m16n8k16).
// V: fp16 B-frag (m16n8k16).
// ---------------------------------------------------------------------------
__global__ __launch_bounds__(256) void qkv_kernel(
    const float* __restrict__ x,
    const float* __restrict__ wq, const float* __restrict__ bq,
    const float* __restrict__ wk, const float* __restrict__ bk,
    const float* __restrict__ wv, const float* __restrict__ bv)
{
    __shared__ float hs[64 * 65];     // normalized input [c][p]
    __shared__ float outs[64 * 65];   // staging [p][o]
    __shared__ float smean[64], srstd[64];

    int tile = blockIdx.x;
    int b    = tile / (NN / 64);
    int n0   = (tile % (NN / 64)) * 64;
    int tid  = threadIdx.x;
    int p    = tid & 63;
    int og   = tid >> 6;

    if (tid < 64) {
        smean[tid] = g_stats[(b * 64 + tid) * 2];
        srstd[tid] = g_stats[(b * 64 + tid) * 2 + 1];
    }
    __syncthreads();

    for (int idx = tid; idx < 64 * 64; idx += 256) {
        int c = idx >> 6, pp = idx & 63;
        hs[c * 65 + pp] = (x[((size_t)b * CC + c) * NN + n0 + pp] - smean[c]) * srstd[c];
    }
    __syncthreads();

    float aq[16], ak[16], av[16];
#pragma unroll
    for (int i = 0; i < 16; i++) {
        int o = og * 16 + i;
        aq[i] = bq[o]; ak[i] = bk[o]; av[i] = bv[o];
    }

    for (int c4 = 0; c4 < 64; c4 += 4) {
        float h0 = hs[(c4 + 0) * 65 + p];
        float h1 = hs[(c4 + 1) * 65 + p];
        float h2 = hs[(c4 + 2) * 65 + p];
        float h3 = hs[(c4 + 3) * 65 + p];
#pragma unroll
        for (int i = 0; i < 16; i++) {
            int o = og * 16 + i;
            float4 w;
            w = *(const float4*)(wq + o * 64 + c4);
            aq[i] += w.x * h0 + w.y * h1 + w.z * h2 + w.w * h3;
            w = *(const float4*)(wk + o * 64 + c4);
            ak[i] += w.x * h0 + w.y * h1 + w.z * h2 + w.w * h3;
            w = *(const float4*)(wv + o * 64 + c4);
            av[i] += w.x * h0 + w.y * h1 + w.z * h2 + w.w * h3;
        }
    }

    const float QSCALE = 0.125f * 1.4426950408889634f;  // C^-0.5 * log2(e)

    // ---- Q: stage scaled, pack fp16 A-frags; layout [b][qblk16][ks4][lane32][rg4] u32
    __syncthreads();
#pragma unroll
    for (int i = 0; i < 16; i++) outs[p * 65 + og * 16 + i] = aq[i] * QSCALE;
    __syncthreads();
    {
        unsigned* qdst = (unsigned*)g_q + ((size_t)b * (NN / 16) + n0 / 16) * 512;
        for (int idx = tid; idx < 2048; idx += 256) {
            int qb = idx >> 9;
            int ks = (idx >> 7) & 3;
            int ln = (idx >> 2) & 31;
            int rg = idx & 3;
            int row = qb * 16 + (ln >> 2) + ((rg & 1) << 3);
            int c0  = ks * 16 + 2 * (ln & 3) + ((rg & 2) << 2);
            qdst[idx] = pack_h2(outs[row * 65 + c0], outs[row * 65 + c0 + 1]);
        }
    }

    // ---- K: stage, pack fp16 B-frags; layout [b][tile][nb8][ks4][lane32][rg2] u32
    __syncthreads();
#pragma unroll
    for (int i = 0; i < 16; i++) outs[p * 65 + og * 16 + i] = ak[i];
    __syncthreads();
    {
        unsigned* kdst = (unsigned*)g_k + ((size_t)b * NT + n0 / 64) * 2048;
        for (int idx = tid; idx < 2048; idx += 256) {
            int nb = idx >> 8;
            int ks = (idx >> 6) & 3;
            int ln = (idx >> 1) & 31;
            int rg = idx & 1;
            int key = nb * 8 + (ln >> 2);
            int kr  = ks * 16 + 2 * (ln & 3) + rg * 8;
            kdst[idx] = pack_h2(outs[key * 65 + kr], outs[key * 65 + kr + 1]);
        }
    }

    // ---- V: stage, pack fp16 B-frags; layout [b][tile][kb4][db8][lane32][rg2] u32
    __syncthreads();
#pragma unroll
    for (int i = 0; i < 16; i++) outs[p * 65 + og * 16 + i] = av[i];
    __syncthreads();
    {
        unsigned* vdst = (unsigned*)g_v + ((size_t)b * NT + n0 / 64) * 2048;
        for (int idx = tid; idx < 2048; idx += 256) {
            int kb = idx >> 9;
            int db = (idx >> 6) & 7;
            int ln = (idx >> 1) & 31;
            int rg = idx & 1;
            int key0 = kb * 16 + ((ln & 3) << 1) + (rg << 3);
            int d    = db * 8 + (ln >> 2);
            vdst[idx] = pack_h2(outs[key0 * 65 + d], outs[(key0 + 1) * 65 + d]);
        }
    }
}

// ---------------------------------------------------------------------------
// Kernel 3: tensor-core flash attention, all fp16 mma.
// 256 threads (8 warps), 32 queries/warp, 64-key tiles double-buffered.
// Scores in log2 domain; P via ex2.f16x2; row-sum l via ones-column mma.
// ---------------------------------------------------------------------------
__global__ void __launch_bounds__(256, 1) attn_kernel() {
    __shared__ uint4 KV[2][1024];   // per buf: K = 512 uint4 (8KB), V = 512 uint4 (8KB)

    int b    = blockIdx.y;
    int w    = threadIdx.x >> 5;
    int lane = threadIdx.x & 31;

    // ---- load Q fragments (registers for whole kernel) ----
    unsigned qa[2][4][4];
    {
        const uint4* qbase = (const uint4*)g_q + ((size_t)b * (NN / 16)) * 128;
        int qblk0 = blockIdx.x * 16 + w * 2;
#pragma unroll
        for (int t = 0; t < 2; t++)
#pragma unroll
            for (int ks = 0; ks < 4; ks++) {
                uint4 v = qbase[((qblk0 + t) * 4 + ks) * 32 + lane];
                qa[t][ks][0] = v.x; qa[t][ks][1] = v.y;
                qa[t][ks][2] = v.z; qa[t][ks][3] = v.w;
            }
    }

    float O[2][9][4];       // db 0..7 = output dims, db 8 = l (ones column)
    float S[2][8][4];
    unsigned P[2][8][2];
    float mrow[2][2];
#pragma unroll
    for (int t = 0; t < 2; t++) {
#pragma unroll
        for (int db = 0; db < 9; db++) {
            O[t][db][0] = 0.f; O[t][db][1] = 0.f; O[t][db][2] = 0.f; O[t][db][3] = 0.f;
        }
        mrow[t][0] = -1e30f; mrow[t][1] = -1e30f;
    }

    // ones-column B fragment for l accumulation (col 0 of extra n8 block)
    unsigned ones = ((lane >> 2) == 0) ? 0x3C003C00u : 0u;
    uint2 vones = make_uint2(ones, ones);

    const uint4* ksrc = (const uint4*)g_k + (size_t)b * NT * 512;
    const uint4* vsrc = (const uint4*)g_v + (size_t)b * NT * 512;

    // prologue: tile 0
    {
        unsigned sb = smem_u32(&KV[0][0]);
        for (int i = threadIdx.x; i < 1024; i += 256) {
            const uint4* src = (i < 512) ? (ksrc + i) : (vsrc + (i - 512));
            cp_async16(sb + i * 16, src);
        }
        cp_commit();
    }

    for (int tl = 0; tl < NT; tl++) {
        int buf = tl & 1;
        if (tl + 1 < NT) {
            unsigned sb = smem_u32(&KV[buf ^ 1][0]);
            const uint4* kb = ksrc + (size_t)(tl + 1) * 512;
            const uint4* vb = vsrc + (size_t)(tl + 1) * 512;
            for (int i = threadIdx.x; i < 1024; i += 256) {
                const uint4* src = (i < 512) ? (kb + i) : (vb + (i - 512));
                cp_async16(sb + i * 16, src);
            }
            cp_commit();
            asm volatile("cp.async.wait_group 1;" ::: "memory");
        } else {
            asm volatile("cp.async.wait_group 0;" ::: "memory");
        }
        __syncthreads();

        const uint2* Kf = (const uint2*)&KV[buf][0];
        const uint2* Vf = (const uint2*)&KV[buf][512];

        // ---- S = Q * K^T (fp16, log2 domain) ----
#pragma unroll
        for (int nb = 0; nb < 8; nb++) {
            uint2 kf[4];
#pragma unroll
            for (int ks = 0; ks < 4; ks++) kf[ks] = Kf[(nb * 4 + ks) * 32 + lane];
#pragma unroll
            for (int t = 0; t < 2; t++) {
                S[t][nb][0] = 0.f; S[t][nb][1] = 0.f; S[t][nb][2] = 0.f; S[t][nb][3] = 0.f;
#pragma unroll
                for (int ks = 0; ks < 4; ks++) mma_f16(S[t][nb], qa[t][ks], kf[ks]);
            }
        }

        // ---- online softmax (log2 domain) ----
#pragma unroll
        for (int t = 0; t < 2; t++)
#pragma unroll
            for (int h = 0; h < 2; h++) {
                float mx = -1e30f;
#pragma unroll
                for (int nb = 0; nb < 8; nb++)
                    mx = fmaxf(mx, fmaxf(S[t][nb][2 * h], S[t][nb][2 * h + 1]));
                mx = fmaxf(mx, __shfl_xor_sync(0xffffffffu, mx, 1));
                mx = fmaxf(mx, __shfl_xor_sync(0xffffffffu, mx, 2));
                float mo = mrow[t][h];
                float mn = fmaxf(mo, mx);
                mrow[t][h] = mn;
                float corr = exp2f(mo - mn);
#pragma unroll
                for (int db = 0; db < 9; db++) {
                    O[t][db][2 * h]     *= corr;
                    O[t][db][2 * h + 1] *= corr;
                }
#pragma unroll
                for (int nb = 0; nb < 8; nb++) {
                    float f0 = S[t][nb][2 * h]     - mn;
                    float f1 = S[t][nb][2 * h + 1] - mn;
                    P[t][nb][h] = ex2_h2(pack_h2(f0, f1));
                }
            }

        // ---- O += P * V (fp16), l via ones column ----
#pragma unroll
        for (int ks = 0; ks < 4; ks++) {
            unsigned pa[2][4];
#pragma unroll
            for (int t = 0; t < 2; t++) {
                pa[t][0] = P[t][2 * ks][0];
                pa[t][1] = P[t][2 * ks][1];
                pa[t][2] = P[t][2 * ks + 1][0];
                pa[t][3] = P[t][2 * ks + 1][1];
            }
#pragma unroll
            for (int db = 0; db < 8; db++) {
                uint2 vb = Vf[(ks * 8 + db) * 32 + lane];
                mma_f16(O[0][db], pa[0], vb);
                mma_f16(O[1][db], pa[1], vb);
            }
            mma_f16(O[0][8], pa[0], vones);
            mma_f16(O[1][8], pa[1], vones);
        }
        __syncthreads();
    }

    // ---- finalize: l lives in O[t][8][2h] at quad-lane 0 ----
    int q0 = blockIdx.x * QBLK + w * 32 + (lane >> 2);
#pragma unroll
    for (int t = 0; t < 2; t++)
#pragma unroll
        for (int h = 0; h < 2; h++) {
            float l = __shfl_sync(0xffffffffu, O[t][8][2 * h], lane & 28);
            float iv = 1.0f / l;
            int q = q0 + t * 16 + h * 8;
            float* op = g_o + ((size_t)b * NN + q) * 64 + (lane & 3) * 2;
#pragma unroll
            for (int db = 0; db < 8; db++) {
                float2 v = make_float2(O[t][db][2 * h] * iv, O[t][db][2 * h + 1] * iv);
                *(float2*)(op + db * 8) = v;
            }
        }
}

// ---------------------------------------------------------------------------
// Kernel 4: output 1x1 conv + residual, weights staged in smem.
// ---------------------------------------------------------------------------
__global__ __launch_bounds__(256) void out_kernel(
    const float* __restrict__ x,
    const float* __restrict__ wo, const float* __restrict__ bo,
    float* __restrict__ out)
{
    __shared__ float osh[64 * 65];
    __shared__ float wsh[64 * 64];

    int tile = blockIdx.x;
    int b    = tile / (NN / 64);
    int n0   = (tile % (NN / 64)) * 64;
    int tid  = threadIdx.x;
    int p    = tid & 63;
    int cg   = tid >> 6;

    for (int idx = tid; idx < 64 * 64; idx += 256) {
        wsh[idx] = wo[idx];
        int pp = idx >> 6, oo = idx & 63;
        osh[pp * 65 + oo] = g_o[((size_t)b * NN + n0 + pp) * 64 + oo];
    }
    __syncthreads();

    float acc[16];
#pragma unroll
    for (int i = 0; i < 16; i++) acc[i] = bo[cg * 16 + i];

    for (int c4 = 0; c4 < 64; c4 += 4) {
        float o0 = osh[p * 65 + c4 + 0];
        float o1 = osh[p * 65 + c4 + 1];
        float o2 = osh[p * 65 + c4 + 2];
        float o3 = osh[p * 65 + c4 + 3];
#pragma unroll
        for (int i = 0; i < 16; i++) {
            int co = cg * 16 + i;
            float4 w = *(const float4*)(wsh + co * 64 + c4);   // broadcast LDS
            acc[i] += w.x * o0 + w.y * o1 + w.z * o2 + w.w * o3;
        }
    }
#pragma unroll
    for (int i = 0; i < 16; i++) {
        int co = cg * 16 + i;
        size_t oidx = ((size_t)b * CC + co) * NN + n0 + p;
        out[oidx] = x[oidx] + acc[i];
    }
}

// ---------------------------------------------------------------------------
extern "C" void kernel_launch(void* const* d_in, const int* in_sizes, int n_in,
                              void* d_out, int out_size)
{
    const float* x  = (const float*)d_in[0];
    const float* wq = (const float*)d_in[1];
    const float* bq = (const float*)d_in[2];
    const float* wk = (const float*)d_in[3];
    const float* bk = (const float*)d_in[4];
    const float* wv = (const float*)d_in[5];
    const float* bv = (const float*)d_in[6];
    const float* wo = (const float*)d_in[7];
    const float* bo = (const float*)d_in[8];
    float* out = (float*)d_out;

    stats_kernel<<<BB * CC, 256>>>(x);
    qkv_kernel<<<BB * (NN / 64), 256>>>(x, wq, bq, wk, bk, wv, bv);
    attn_kernel<<<dim3(NN / QBLK, BB), 256>>>();
    out_kernel<<<BB * (NN / 64), 256>>>(x, wo, bo, out);
}

// round 4
// speedup vs baseline: 10.1888x; 1.0763x over previous
#include <cuda_runtime.h>
#include <cuda_fp16.h>
#include <cuda_bf16.h>
#include <math.h>

#define BB 4
#define CC 64
#define NN 9216       // 96*96
#define NT (NN/64)    // 144 64-key packing tiles
#define QBLK 128      // queries per attention block (4 warps x 32)
#define NRND (NN/128) // 72 staging rounds of 128 keys

// Scratch (static device arrays; no allocation allowed)
__device__ float g_stats[BB * CC * 2];           // mean, rstd per (b,c)
__device__ float g_q[(size_t)BB * NN * CC / 2];  // fp16 A-frag packed (m16n8k16)
__device__ float g_k[(size_t)BB * NN * CC / 2];  // fp16 B-frag packed
__device__ float g_v[(size_t)BB * NN * CC / 2];  // fp16 B-frag packed
__device__ float g_o[(size_t)BB * NN * CC];      // attention out [B,N,64] fp32

// ---------------------------------------------------------------------------
// helpers
// ---------------------------------------------------------------------------
static __device__ __forceinline__ unsigned smem_u32(const void* p) {
    return (unsigned)__cvta_generic_to_shared(p);
}
static __device__ __forceinline__ void cp_async16(unsigned dst, const void* src) {
    asm volatile("cp.async.cg.shared.global [%0], [%1], 16;" :: "r"(dst), "l"(src) : "memory");
}
static __device__ __forceinline__ void cp_commit() {
    asm volatile("cp.async.commit_group;" ::: "memory");
}
static __device__ __forceinline__ unsigned pack_h2(float a, float b) {
    __half2 h = __floats2half2_rn(a, b);
    return *reinterpret_cast<unsigned*>(&h);
}
static __device__ __forceinline__ unsigned ex2_h2(unsigned h) {
    unsigned r;
    asm("ex2.approx.f16x2 %0, %1;" : "=r"(r) : "r"(h));
    return r;
}
static __device__ __forceinline__ void mma_f16(float* d, const unsigned* a, uint2 b) {
    asm volatile(
        "mma.sync.aligned.m16n8k16.row.col.f32.f16.f16.f32 "
        "{%0,%1,%2,%3},{%4,%5,%6,%7},{%8,%9},{%0,%1,%2,%3};"
        : "+f"(d[0]), "+f"(d[1]), "+f"(d[2]), "+f"(d[3])
        : "r"(a[0]), "r"(a[1]), "r"(a[2]), "r"(a[3]),
          "r"(b.x), "r"(b.y));
}

// ---------------------------------------------------------------------------
// Kernel 1: instance-norm statistics only. One block per (b,c).
// ---------------------------------------------------------------------------
__global__ __launch_bounds__(256) void stats_kernel(const float* __restrict__ x) {
    int bc = blockIdx.x;
    const float4* xp = (const float4*)(x + (size_t)bc * NN);
    int tid = threadIdx.x;

    float s = 0.f, ss = 0.f;
    for (int i = tid; i < NN / 4; i += 256) {
        float4 v = xp[i];
        s  += v.x + v.y + v.z + v.w;
        ss += v.x * v.x + v.y * v.y + v.z * v.z + v.w * v.w;
    }
    __shared__ float rs[256], rss[256];
    rs[tid] = s; rss[tid] = ss;
    __syncthreads();
    for (int off = 128; off > 0; off >>= 1) {
        if (tid < off) { rs[tid] += rs[tid + off]; rss[tid] += rss[tid + off]; }
        __syncthreads();
    }
    if (tid == 0) {
        float mean = rs[0] * (1.0f / NN);
        float var  = rss[0] * (1.0f / NN) - mean * mean;
        g_stats[bc * 2]     = mean;
        g_stats[bc * 2 + 1] = rsqrtf(var + 1e-5f);
    }
}

// ---------------------------------------------------------------------------
// Kernel 2: fused norm + Q/K/V 1x1 convs + fp16 fragment packing.
// ---------------------------------------------------------------------------
__global__ __launch_bounds__(256) void qkv_kernel(
    const float* __restrict__ x,
    const float* __restrict__ wq, const float* __restrict__ bq,
    const float* __restrict__ wk, const float* __restrict__ bk,
    const float* __restrict__ wv, const float* __restrict__ bv)
{
    __shared__ float hs[64 * 65];
    __shared__ float outs[64 * 65];
    __shared__ float smean[64], srstd[64];

    int tile = blockIdx.x;
    int b    = tile / (NN / 64);
    int n0   = (tile % (NN / 64)) * 64;
    int tid  = threadIdx.x;
    int p    = tid & 63;
    int og   = tid >> 6;

    if (tid < 64) {
        smean[tid] = g_stats[(b * 64 + tid) * 2];
        srstd[tid] = g_stats[(b * 64 + tid) * 2 + 1];
    }
    __syncthreads();

    for (int idx = tid; idx < 64 * 64; idx += 256) {
        int c = idx >> 6, pp = idx & 63;
        hs[c * 65 + pp] = (x[((size_t)b * CC + c) * NN + n0 + pp] - smean[c]) * srstd[c];
    }
    __syncthreads();

    float aq[16], ak[16], av[16];
#pragma unroll
    for (int i = 0; i < 16; i++) {
        int o = og * 16 + i;
        aq[i] = bq[o]; ak[i] = bk[o]; av[i] = bv[o];
    }

    for (int c4 = 0; c4 < 64; c4 += 4) {
        float h0 = hs[(c4 + 0) * 65 + p];
        float h1 = hs[(c4 + 1) * 65 + p];
        float h2 = hs[(c4 + 2) * 65 + p];
        float h3 = hs[(c4 + 3) * 65 + p];
#pragma unroll
        for (int i = 0; i < 16; i++) {
            int o = og * 16 + i;
            float4 w;
            w = *(const float4*)(wq + o * 64 + c4);
            aq[i] += w.x * h0 + w.y * h1 + w.z * h2 + w.w * h3;
            w = *(const float4*)(wk + o * 64 + c4);
            ak[i] += w.x * h0 + w.y * h1 + w.z * h2 + w.w * h3;
            w = *(const float4*)(wv + o * 64 + c4);
            av[i] += w.x * h0 + w.y * h1 + w.z * h2 + w.w * h3;
        }
    }

    const float QSCALE = 0.125f * 1.4426950408889634f;  // C^-0.5 * log2(e)

    // ---- Q: fp16 A-frags; layout [b][qblk16][ks4][lane32][rg4] u32
    __syncthreads();
#pragma unroll
    for (int i = 0; i < 16; i++) outs[p * 65 + og * 16 + i] = aq[i] * QSCALE;
    __syncthreads();
    {
        unsigned* qdst = (unsigned*)g_q + ((size_t)b * (NN / 16) + n0 / 16) * 512;
        for (int idx = tid; idx < 2048; idx += 256) {
            int qb = idx >> 9;
            int ks = (idx >> 7) & 3;
            int ln = (idx >> 2) & 31;
            int rg = idx & 3;
            int row = qb * 16 + (ln >> 2) + ((rg & 1) << 3);
            int c0  = ks * 16 + 2 * (ln & 3) + ((rg & 2) << 2);
            qdst[idx] = pack_h2(outs[row * 65 + c0], outs[row * 65 + c0 + 1]);
        }
    }

    // ---- K: fp16 B-frags; layout [b][tile64][nb8][ks4][lane32][rg2] u32
    __syncthreads();
#pragma unroll
    for (int i = 0; i < 16; i++) outs[p * 65 + og * 16 + i] = ak[i];
    __syncthreads();
    {
        unsigned* kdst = (unsigned*)g_k + ((size_t)b * NT + n0 / 64) * 2048;
        for (int idx = tid; idx < 2048; idx += 256) {
            int nb = idx >> 8;
            int ks = (idx >> 6) & 3;
            int ln = (idx >> 1) & 31;
            int rg = idx & 1;
            int key = nb * 8 + (ln >> 2);
            int kr  = ks * 16 + 2 * (ln & 3) + rg * 8;
            kdst[idx] = pack_h2(outs[key * 65 + kr], outs[key * 65 + kr + 1]);
        }
    }

    // ---- V: fp16 B-frags; layout [b][tile64][kb4][db8][lane32][rg2] u32
    __syncthreads();
#pragma unroll
    for (int i = 0; i < 16; i++) outs[p * 65 + og * 16 + i] = av[i];
    __syncthreads();
    {
        unsigned* vdst = (unsigned*)g_v + ((size_t)b * NT + n0 / 64) * 2048;
        for (int idx = tid; idx < 2048; idx += 256) {
            int kb = idx >> 9;
            int db = (idx >> 6) & 7;
            int ln = (idx >> 1) & 31;
            int rg = idx & 1;
            int key0 = kb * 16 + ((ln & 3) << 1) + (rg << 3);
            int d    = db * 8 + (ln >> 2);
            vdst[idx] = pack_h2(outs[key0 * 65 + d], outs[(key0 + 1) * 65 + d]);
        }
    }
}

// ---------------------------------------------------------------------------
// Kernel 3: tensor-core flash attention, fp16 mma.
// 128 threads (4 warps), 2 CTAs/SM. 128-key staging rounds, double-buffered,
// ONE __syncthreads per round. Lazy softmax rescale (warp-uniform skip).
// Dynamic smem: 2 bufs x (16KB K + 16KB V) = 64KB.
// ---------------------------------------------------------------------------
__global__ void __launch_bounds__(128, 2) attn_kernel() {
    extern __shared__ uint4 KV[];   // [2][2048]

    int b    = blockIdx.y;
    int w    = threadIdx.x >> 5;
    int lane = threadIdx.x & 31;

    // ---- Q fragments (registers for whole kernel) ----
    unsigned qa[2][4][4];
    {
        const uint4* qbase = (const uint4*)g_q + ((size_t)b * (NN / 16)) * 128;
        int qblk0 = blockIdx.x * 8 + w * 2;
#pragma unroll
        for (int t = 0; t < 2; t++)
#pragma unroll
            for (int ks = 0; ks < 4; ks++) {
                uint4 v = qbase[((qblk0 + t) * 4 + ks) * 32 + lane];
                qa[t][ks][0] = v.x; qa[t][ks][1] = v.y;
                qa[t][ks][2] = v.z; qa[t][ks][3] = v.w;
            }
    }

    float O[2][9][4];       // db 0..7 = output dims, db 8 = l (ones column)
    float S[2][8][4];
    unsigned P[2][8][2];
    float mrow[2][2];
#pragma unroll
    for (int t = 0; t < 2; t++) {
#pragma unroll
        for (int db = 0; db < 9; db++) {
            O[t][db][0] = 0.f; O[t][db][1] = 0.f; O[t][db][2] = 0.f; O[t][db][3] = 0.f;
        }
        mrow[t][0] = -1e30f; mrow[t][1] = -1e30f;
    }

    unsigned ones = ((lane >> 2) == 0) ? 0x3C003C00u : 0u;
    uint2 vones = make_uint2(ones, ones);

    const uint4* ksrc = (const uint4*)g_k + (size_t)b * NT * 512;
    const uint4* vsrc = (const uint4*)g_v + (size_t)b * NT * 512;

    // prologue: stage round 0 (128 keys: K 1024 uint4 + V 1024 uint4)
    {
        unsigned sb = smem_u32(&KV[0]);
        for (int i = threadIdx.x; i < 2048; i += 128) {
            const uint4* src = (i < 1024) ? (ksrc + i) : (vsrc + (i - 1024));
            cp_async16(sb + i * 16, src);
        }
        cp_commit();
    }

    for (int rd = 0; rd < NRND; rd++) {
        int buf = rd & 1;
        asm volatile("cp.async.wait_group 0;" ::: "memory");
        __syncthreads();   // all warps done with buf^1; safe to overwrite

        if (rd + 1 < NRND) {
            unsigned sb = smem_u32(&KV[(buf ^ 1) * 2048]);
            const uint4* kb = ksrc + (size_t)(rd + 1) * 1024;
            const uint4* vb = vsrc + (size_t)(rd + 1) * 1024;
            for (int i = threadIdx.x; i < 2048; i += 128) {
                const uint4* src = (i < 1024) ? (kb + i) : (vb + (i - 1024));
                cp_async16(sb + i * 16, src);
            }
            cp_commit();
        }

        // ---- compute: two 64-key sub-tiles ----
#pragma unroll
        for (int st = 0; st < 2; st++) {
            const uint2* Kf = (const uint2*)&KV[(size_t)buf * 2048]        + st * 1024;
            const uint2* Vf = (const uint2*)&KV[(size_t)buf * 2048 + 1024] + st * 1024;

            // S = Q * K^T (fp16, log2 domain)
#pragma unroll
            for (int nb = 0; nb < 8; nb++) {
                uint2 kf[4];
#pragma unroll
                for (int ks = 0; ks < 4; ks++) kf[ks] = Kf[(nb * 4 + ks) * 32 + lane];
#pragma unroll
                for (int t = 0; t < 2; t++) {
                    S[t][nb][0] = 0.f; S[t][nb][1] = 0.f; S[t][nb][2] = 0.f; S[t][nb][3] = 0.f;
#pragma unroll
                    for (int ks = 0; ks < 4; ks++) mma_f16(S[t][nb], qa[t][ks], kf[ks]);
                }
            }

            // online softmax (log2 domain, lazy rescale)
#pragma unroll
            for (int t = 0; t < 2; t++)
#pragma unroll
                for (int h = 0; h < 2; h++) {
                    float mx = -1e30f;
#pragma unroll
                    for (int nb = 0; nb < 8; nb++)
                        mx = fmaxf(mx, fmaxf(S[t][nb][2 * h], S[t][nb][2 * h + 1]));
                    mx = fmaxf(mx, __shfl_xor_sync(0xffffffffu, mx, 1));
                    mx = fmaxf(mx, __shfl_xor_sync(0xffffffffu, mx, 2));
                    float mo = mrow[t][h];
                    if (__any_sync(0xffffffffu, mx > mo)) {
                        float mn = fmaxf(mo, mx);
                        mrow[t][h] = mn;
                        float corr = exp2f(mo - mn);   // lanes w/o update: exp2(0)=1 exact
#pragma unroll
                        for (int db = 0; db < 9; db++) {
                            O[t][db][2 * h]     *= corr;
                            O[t][db][2 * h + 1] *= corr;
                        }
                        mo = mn;
                    }
#pragma unroll
                    for (int nb = 0; nb < 8; nb++) {
                        float f0 = S[t][nb][2 * h]     - mo;
                        float f1 = S[t][nb][2 * h + 1] - mo;
                        P[t][nb][h] = ex2_h2(pack_h2(f0, f1));
                    }
                }

            // O += P * V (fp16), l via ones column
#pragma unroll
            for (int ks = 0; ks < 4; ks++) {
                unsigned pa[2][4];
#pragma unroll
                for (int t = 0; t < 2; t++) {
                    pa[t][0] = P[t][2 * ks][0];
                    pa[t][1] = P[t][2 * ks][1];
                    pa[t][2] = P[t][2 * ks + 1][0];
                    pa[t][3] = P[t][2 * ks + 1][1];
                }
#pragma unroll
                for (int db = 0; db < 8; db++) {
                    uint2 vb = Vf[(ks * 8 + db) * 32 + lane];
                    mma_f16(O[0][db], pa[0], vb);
                    mma_f16(O[1][db], pa[1], vb);
                }
                mma_f16(O[0][8], pa[0], vones);
                mma_f16(O[1][8], pa[1], vones);
            }
        }
    }

    // ---- finalize: l lives in O[t][8][2h] at quad-lane 0 ----
    int q0 = blockIdx.x * QBLK + w * 32 + (lane >> 2);
#pragma unroll
    for (int t = 0; t < 2; t++)
#pragma unroll
        for (int h = 0; h < 2; h++) {
            float l = __shfl_sync(0xffffffffu, O[t][8][2 * h], lane & 28);
            float iv = 1.0f / l;
            int q = q0 + t * 16 + h * 8;
            float* op = g_o + ((size_t)b * NN + q) * 64 + (lane & 3) * 2;
#pragma unroll
            for (int db = 0; db < 8; db++) {
                float2 v = make_float2(O[t][db][2 * h] * iv, O[t][db][2 * h + 1] * iv);
                *(float2*)(op + db * 8) = v;
            }
        }
}

// ---------------------------------------------------------------------------
// Kernel 4: output 1x1 conv + residual, weights staged in smem.
// ---------------------------------------------------------------------------
__global__ __launch_bounds__(256) void out_kernel(
    const float* __restrict__ x,
    const float* __restrict__ wo, const float* __restrict__ bo,
    float* __restrict__ out)
{
    __shared__ float osh[64 * 65];
    __shared__ float wsh[64 * 64];

    int tile = blockIdx.x;
    int b    = tile / (NN / 64);
    int n0   = (tile % (NN / 64)) * 64;
    int tid  = threadIdx.x;
    int p    = tid & 63;
    int cg   = tid >> 6;

    for (int idx = tid; idx < 64 * 64; idx += 256) {
        wsh[idx] = wo[idx];
        int pp = idx >> 6, oo = idx & 63;
        osh[pp * 65 + oo] = g_o[((size_t)b * NN + n0 + pp) * 64 + oo];
    }
    __syncthreads();

    float acc[16];
#pragma unroll
    for (int i = 0; i < 16; i++) acc[i] = bo[cg * 16 + i];

    for (int c4 = 0; c4 < 64; c4 += 4) {
        float o0 = osh[p * 65 + c4 + 0];
        float o1 = osh[p * 65 + c4 + 1];
        float o2 = osh[p * 65 + c4 + 2];
        float o3 = osh[p * 65 + c4 + 3];
#pragma unroll
        for (int i = 0; i < 16; i++) {
            int co = cg * 16 + i;
            float4 w = *(const float4*)(wsh + co * 64 + c4);
            acc[i] += w.x * o0 + w.y * o1 + w.z * o2 + w.w * o3;
        }
    }
#pragma unroll
    for (int i = 0; i < 16; i++) {
        int co = cg * 16 + i;
        size_t oidx = ((size_t)b * CC + co) * NN + n0 + p;
        out[oidx] = x[oidx] + acc[i];
    }
}

// ---------------------------------------------------------------------------
extern "C" void kernel_launch(void* const* d_in, const int* in_sizes, int n_in,
                              void* d_out, int out_size)
{
    const float* x  = (const float*)d_in[0];
    const float* wq = (const float*)d_in[1];
    const float* bq = (const float*)d_in[2];
    const float* wk = (const float*)d_in[3];
    const float* bk = (const float*)d_in[4];
    const float* wv = (const float*)d_in[5];
    const float* bv = (const float*)d_in[6];
    const float* wo = (const float*)d_in[7];
    const float* bo = (const float*)d_in[8];
    float* out = (float*)d_out;

    static bool attr_set = false;
    if (!attr_set) {
        cudaFuncSetAttribute(attn_kernel,
                             cudaFuncAttributeMaxDynamicSharedMemorySize, 65536);
        attr_set = true;
    }

    stats_kernel<<<BB * CC, 256>>>(x);
    qkv_kernel<<<BB * (NN / 64), 256>>>(x, wq, bq, wk, bk, wv, bv);
    attn_kernel<<<dim3(NN / QBLK, BB), 128, 65536>>>();
    out_kernel<<<BB * (NN / 64), 256>>>(x, wo, bo, out);
}

// round 6
// speedup vs baseline: 12.3928x; 1.2163x over previous
#include <cuda_runtime.h>
#include <cuda_fp16.h>
#include <cuda_bf16.h>
#include <math.h>

#define BB 4
#define CC 64
#define NN 9216       // 96*96
#define NT (NN/64)    // 144 64-key packing tiles
#define QBLK 128      // queries per attention block (4 warps x 32)
#define NRND (NN/128) // 72 staging rounds of 128 keys

// Scratch (static device arrays; no allocation allowed)
__device__ float g_stats[BB * CC * 2];           // mean, rstd per (b,c)
__device__ float g_q[(size_t)BB * NN * CC / 2];  // fp16 A-frag packed (m16n8k16)
__device__ float g_k[(size_t)BB * NN * CC / 2];  // fp16 B-frag packed (uint4 groups)
__device__ float g_v[(size_t)BB * NN * CC / 2];  // fp16 B-frag packed (uint4 groups)
__device__ float g_o[(size_t)BB * NN * CC];      // attention out [B,N,64] fp32

// ---------------------------------------------------------------------------
// helpers
// ---------------------------------------------------------------------------
static __device__ __forceinline__ unsigned smem_u32(const void* p) {
    return (unsigned)__cvta_generic_to_shared(p);
}
static __device__ __forceinline__ void cp_async16(unsigned dst, const void* src) {
    asm volatile("cp.async.cg.shared.global [%0], [%1], 16;" :: "r"(dst), "l"(src) : "memory");
}
static __device__ __forceinline__ void cp_commit() {
    asm volatile("cp.async.commit_group;" ::: "memory");
}
static __device__ __forceinline__ unsigned pack_h2(float a, float b) {
    __half2 h = __floats2half2_rn(a, b);
    return *reinterpret_cast<unsigned*>(&h);
}
static __device__ __forceinline__ unsigned ex2_h2(unsigned h) {
    unsigned r;
    asm("ex2.approx.f16x2 %0, %1;" : "=r"(r) : "r"(h));
    return r;
}
static __device__ __forceinline__ void mma_f16(float* d, const unsigned* a, uint2 b) {
    asm volatile(
        "mma.sync.aligned.m16n8k16.row.col.f32.f16.f16.f32 "
        "{%0,%1,%2,%3},{%4,%5,%6,%7},{%8,%9},{%0,%1,%2,%3};"
        : "+f"(d[0]), "+f"(d[1]), "+f"(d[2]), "+f"(d[3])
        : "r"(a[0]), "r"(a[1]), "r"(a[2]), "r"(a[3]),
          "r"(b.x), "r"(b.y));
}

// ---------------------------------------------------------------------------
// Kernel 1: instance-norm statistics only. One block per (b,c).
// ---------------------------------------------------------------------------
__global__ __launch_bounds__(256) void stats_kernel(const float* __restrict__ x) {
    int bc = blockIdx.x;
    const float4* xp = (const float4*)(x + (size_t)bc * NN);
    int tid = threadIdx.x;

    float s = 0.f, ss = 0.f;
    for (int i = tid; i < NN / 4; i += 256) {
        float4 v = xp[i];
        s  += v.x + v.y + v.z + v.w;
        ss += v.x * v.x + v.y * v.y + v.z * v.z + v.w * v.w;
    }
    __shared__ float rs[256], rss[256];
    rs[tid] = s; rss[tid] = ss;
    __syncthreads();
    for (int off = 128; off > 0; off >>= 1) {
        if (tid < off) { rs[tid] += rs[tid + off]; rss[tid] += rss[tid + off]; }
        __syncthreads();
    }
    if (tid == 0) {
        float mean = rs[0] * (1.0f / NN);
        float var  = rss[0] * (1.0f / NN) - mean * mean;
        g_stats[bc * 2]     = mean;
        g_stats[bc * 2 + 1] = rsqrtf(var + 1e-5f);
    }
}

// ---------------------------------------------------------------------------
// Kernel 2: fused norm + Q/K/V 1x1 convs via fp16 tensor cores + frag packing.
// 256 threads = 8 warps; warp w: o-tile = w&3 (16 rows), nb-half = w>>2 (4 n8).
// smem (dynamic): outs f32 [64*65] | hsh u32 [64*36] | wsh u32 [3][64*36]
// ---------------------------------------------------------------------------
#define QS_OUTS 0
#define QS_HSH  16640
#define QS_WSH  25856
#define QS_MEAN 53504
#define QS_RSTD 53760
#define QKV_SMEM 54016

__global__ __launch_bounds__(256) void qkv_kernel(
    const float* __restrict__ x,
    const float* __restrict__ wq, const float* __restrict__ bq,
    const float* __restrict__ wk, const float* __restrict__ bk,
    const float* __restrict__ wv, const float* __restrict__ bv)
{
    extern __shared__ char smem[];
    float*    outs  = (float*)(smem + QS_OUTS);
    unsigned* hsh   = (unsigned*)(smem + QS_HSH);
    unsigned* wsh   = (unsigned*)(smem + QS_WSH);
    float*    smean = (float*)(smem + QS_MEAN);
    float*    srstd = (float*)(smem + QS_RSTD);

    int tile = blockIdx.x;
    int b    = tile / (NN / 64);
    int n0   = (tile % (NN / 64)) * 64;
    int tid  = threadIdx.x;
    int w    = tid >> 5;
    int lane = tid & 31;
    int rp   = lane >> 2;     // 0..7
    int m    = lane & 3;      // 0..3
    int otile = w & 3;
    int nbb   = (w >> 2) * 4;

    if (tid < 64) {
        smean[tid] = g_stats[(b * 64 + tid) * 2];
        srstd[tid] = g_stats[(b * 64 + tid) * 2 + 1];
    }
    __syncthreads();

    // ---- stage normalized input as fp16 pairs: hsh[p][cpair], row pad 36
    for (int idx = tid; idx < 2048; idx += 256) {
        int cp = idx >> 6, p = idx & 63;
        float v0 = (x[((size_t)b * CC + 2 * cp)     * NN + n0 + p] - smean[2 * cp])     * srstd[2 * cp];
        float v1 = (x[((size_t)b * CC + 2 * cp + 1) * NN + n0 + p] - smean[2 * cp + 1]) * srstd[2 * cp + 1];
        hsh[p * 36 + cp] = pack_h2(v0, v1);
    }
    // ---- stage weights as fp16 pairs: wsh[mat][o][cpair], row pad 36
    for (int idx = tid; idx < 6144; idx += 256) {
        int mat = idx >> 11;
        int rem = idx & 2047;
        int o = rem >> 5, cp = rem & 31;
        const float* wsrc = (mat == 0) ? wq : (mat == 1) ? wk : wv;
        float2 wv2 = *(const float2*)(wsrc + o * 64 + 2 * cp);
        wsh[mat * 2304 + o * 36 + cp] = pack_h2(wv2.x, wv2.y);
    }
    __syncthreads();

    const float QSCALE = 0.125f * 1.4426950408889634f;  // C^-0.5 * log2(e)
    size_t qbase = ((size_t)b * (NN / 16) + n0 / 16) * 512;
    size_t kvtile = ((size_t)b * NT + n0 / 64) * 2048;

#pragma unroll
    for (int mat = 0; mat < 3; mat++) {
        // ---- GEMM: out[o][p] = W[o][:] . h[:][p], fp16 mma
        float acc[4][4];
#pragma unroll
        for (int nb = 0; nb < 4; nb++) {
            acc[nb][0] = 0.f; acc[nb][1] = 0.f; acc[nb][2] = 0.f; acc[nb][3] = 0.f;
        }
        const unsigned* wm = wsh + mat * 2304;
#pragma unroll
        for (int k = 0; k < 4; k++) {
            unsigned a[4];
            int abase = (otile * 16 + rp) * 36 + k * 8 + m;
            a[0] = wm[abase];
            a[1] = wm[abase + 8 * 36];
            a[2] = wm[abase + 4];
            a[3] = wm[abase + 8 * 36 + 4];
#pragma unroll
            for (int nb = 0; nb < 4; nb++) {
                int p = (nbb + nb) * 8 + rp;
                unsigned b0 = hsh[p * 36 + k * 8 + m];
                unsigned b1 = hsh[p * 36 + k * 8 + m + 4];
                mma_f16(acc[nb], a, make_uint2(b0, b1));
            }
        }

        // ---- stage to outs[p][o] (+bias, Q scaled)
        __syncthreads();   // previous matrix's pack finished with outs
        const float* bias = (mat == 0) ? bq : (mat == 1) ? bk : bv;
        float scale = (mat == 0) ? QSCALE : 1.0f;
        float b0v = bias[otile * 16 + rp];
        float b1v = bias[otile * 16 + rp + 8];
        int o0 = otile * 16 + rp;
#pragma unroll
        for (int nb = 0; nb < 4; nb++) {
            int p0 = (nbb + nb) * 8 + 2 * m;
            outs[p0 * 65 + o0]           = (acc[nb][0] + b0v) * scale;
            outs[(p0 + 1) * 65 + o0]     = (acc[nb][1] + b0v) * scale;
            outs[p0 * 65 + o0 + 8]       = (acc[nb][2] + b1v) * scale;
            outs[(p0 + 1) * 65 + o0 + 8] = (acc[nb][3] + b1v) * scale;
        }
        __syncthreads();

        // ---- pack to global fragment layouts
        if (mat == 0) {
            // Q: fp16 A-frags [b][qblk16][ks4][lane32][rg4] u32
            unsigned* qdst = (unsigned*)g_q + qbase;
            for (int idx = tid; idx < 2048; idx += 256) {
                int qb = idx >> 9;
                int ks = (idx >> 7) & 3;
                int ln = (idx >> 2) & 31;
                int rg = idx & 3;
                int row = qb * 16 + (ln >> 2) + ((rg & 1) << 3);
                int c0  = ks * 16 + 2 * (ln & 3) + ((rg & 2) << 2);
                qdst[idx] = pack_h2(outs[row * 65 + c0], outs[row * 65 + c0 + 1]);
            }
        } else if (mat == 1) {
            // K: fp16 B-frags, uint4 groups [nb8][pair2][lane32][q4] u32
            unsigned* kdst = (unsigned*)g_k + kvtile;
            for (int idx = tid; idx < 2048; idx += 256) {
                int nb   = idx >> 8;
                int pair = (idx >> 7) & 1;
                int ln   = (idx >> 2) & 31;
                int q2   = idx & 3;
                int ks = pair * 2 + (q2 >> 1);
                int rg = q2 & 1;
                int key = nb * 8 + (ln >> 2);
                int kr  = ks * 16 + 2 * (ln & 3) + rg * 8;
                kdst[idx] = pack_h2(outs[key * 65 + kr], outs[key * 65 + kr + 1]);
            }
        } else {
            // V: fp16 B-frags, uint4 groups [kb4][j4][lane32][q4] u32
            unsigned* vdst = (unsigned*)g_v + kvtile;
            for (int idx = tid; idx < 2048; idx += 256) {
                int kb = idx >> 9;
                int j  = (idx >> 7) & 3;
                int ln = (idx >> 2) & 31;
                int q2 = idx & 3;
                int db = 2 * j + (q2 >> 1);
                int rg = q2 & 1;
                int key0 = kb * 16 + ((ln & 3) << 1) + (rg << 3);
                int d    = db * 8 + (ln >> 2);
                vdst[idx] = pack_h2(outs[key0 * 65 + d], outs[(key0 + 1) * 65 + d]);
            }
        }
    }
}

// ---------------------------------------------------------------------------
// Kernel 3: tensor-core flash attention, fp16 mma.
// 128 threads (4 warps), 2 CTAs/SM. 128-key staging rounds, double-buffered,
// ONE __syncthreads per round. Lazy softmax rescale. uint4 fragment loads.
// Dynamic smem: 2 bufs x (16KB K + 16KB V) = 64KB.
// ---------------------------------------------------------------------------
__global__ void __launch_bounds__(128, 2) attn_kernel() {
    extern __shared__ uint4 KV[];   // [2][2048]

    int b    = blockIdx.y;
    int w    = threadIdx.x >> 5;
    int lane = threadIdx.x & 31;

    // ---- Q fragments (registers for whole kernel) ----
    unsigned qa[2][4][4];
    {
        const uint4* qbase = (const uint4*)g_q + ((size_t)b * (NN / 16)) * 128;
        int qblk0 = blockIdx.x * 8 + w * 2;
#pragma unroll
        for (int t = 0; t < 2; t++)
#pragma unroll
            for (int ks = 0; ks < 4; ks++) {
                uint4 v = qbase[((qblk0 + t) * 4 + ks) * 32 + lane];
                qa[t][ks][0] = v.x; qa[t][ks][1] = v.y;
                qa[t][ks][2] = v.z; qa[t][ks][3] = v.w;
            }
    }

    float O[2][9][4];       // db 0..7 = output dims, db 8 = l (ones column)
    float S[2][8][4];
    unsigned P[2][8][2];
    float mrow[2][2];
#pragma unroll
    for (int t = 0; t < 2; t++) {
#pragma unroll
        for (int db = 0; db < 9; db++) {
            O[t][db][0] = 0.f; O[t][db][1] = 0.f; O[t][db][2] = 0.f; O[t][db][3] = 0.f;
        }
        mrow[t][0] = -1e30f; mrow[t][1] = -1e30f;
    }

    unsigned ones = ((lane >> 2) == 0) ? 0x3C003C00u : 0u;
    uint2 vones = make_uint2(ones, ones);

    const uint4* ksrc = (const uint4*)g_k + (size_t)b * NT * 512;
    const uint4* vsrc = (const uint4*)g_v + (size_t)b * NT * 512;

    // prologue: stage round 0 (128 keys: K 1024 uint4 + V 1024 uint4)
    {
        unsigned sb = smem_u32(&KV[0]);
        for (int i = threadIdx.x; i < 2048; i += 128) {
            const uint4* src = (i < 1024) ? (ksrc + i) : (vsrc + (i - 1024));
            cp_async16(sb + i * 16, src);
        }
        cp_commit();
    }

    for (int rd = 0; rd < NRND; rd++) {
        int buf = rd & 1;
        asm volatile("cp.async.wait_group 0;" ::: "memory");
        __syncthreads();   // all warps done with buf^1; safe to overwrite

        if (rd + 1 < NRND) {
            unsigned sb = smem_u32(&KV[(buf ^ 1) * 2048]);
            const uint4* kb = ksrc + (size_t)(rd + 1) * 1024;
            const uint4* vb = vsrc + (size_t)(rd + 1) * 1024;
            for (int i = threadIdx.x; i < 2048; i += 128) {
                const uint4* src = (i < 1024) ? (kb + i) : (vb + (i - 1024));
                cp_async16(sb + i * 16, src);
            }
            cp_commit();
        }

        // ---- compute: two 64-key sub-tiles ----
#pragma unroll
        for (int st = 0; st < 2; st++) {
            const uint4* Kf4 = &KV[(size_t)buf * 2048]        + st * 512;
            const uint4* Vf4 = &KV[(size_t)buf * 2048 + 1024] + st * 512;

            // S = Q * K^T (fp16, log2 domain)
#pragma unroll
            for (int nb = 0; nb < 8; nb++) {
                uint4 A = Kf4[(nb * 2 + 0) * 32 + lane];
                uint4 Bv = Kf4[(nb * 2 + 1) * 32 + lane];
                uint2 kf[4];
                kf[0] = make_uint2(A.x, A.y);
                kf[1] = make_uint2(A.z, A.w);
                kf[2] = make_uint2(Bv.x, Bv.y);
                kf[3] = make_uint2(Bv.z, Bv.w);
#pragma unroll
                for (int t = 0; t < 2; t++) {
                    S[t][nb][0] = 0.f; S[t][nb][1] = 0.f; S[t][nb][2] = 0.f; S[t][nb][3] = 0.f;
#pragma unroll
                    for (int ks = 0; ks < 4; ks++) mma_f16(S[t][nb], qa[t][ks], kf[ks]);
                }
            }

            // online softmax (log2 domain, lazy rescale)
#pragma unroll
            for (int t = 0; t < 2; t++)
#pragma unroll
                for (int h = 0; h < 2; h++) {
                    float mx = -1e30f;
#pragma unroll
                    for (int nb = 0; nb < 8; nb++)
                        mx = fmaxf(mx, fmaxf(S[t][nb][2 * h], S[t][nb][2 * h + 1]));
                    mx = fmaxf(mx, __shfl_xor_sync(0xffffffffu, mx, 1));
                    mx = fmaxf(mx, __shfl_xor_sync(0xffffffffu, mx, 2));
                    float mo = mrow[t][h];
                    if (__any_sync(0xffffffffu, mx > mo)) {
                        float mn = fmaxf(mo, mx);
                        mrow[t][h] = mn;
                        float corr = exp2f(mo - mn);   // lanes w/o update: exp2(0)=1 exact
#pragma unroll
                        for (int db = 0; db < 9; db++) {
                            O[t][db][2 * h]     *= corr;
                            O[t][db][2 * h + 1] *= corr;
                        }
                        mo = mn;
                    }
#pragma unroll
                    for (int nb = 0; nb < 8; nb++) {
                        float f0 = S[t][nb][2 * h]     - mo;
                        float f1 = S[t][nb][2 * h + 1] - mo;
                        P[t][nb][h] = ex2_h2(pack_h2(f0, f1));
                    }
                }

            // O += P * V (fp16), l via ones column
#pragma unroll
            for (int ks = 0; ks < 4; ks++) {
                unsigned pa[2][4];
#pragma unroll
                for (int t = 0; t < 2; t++) {
                    pa[t][0] = P[t][2 * ks][0];
                    pa[t][1] = P[t][2 * ks][1];
                    pa[t][2] = P[t][2 * ks + 1][0];
                    pa[t][3] = P[t][2 * ks + 1][1];
                }
#pragma unroll
                for (int j = 0; j < 4; j++) {
                    uint4 Vj = Vf4[(ks * 4 + j) * 32 + lane];
                    uint2 v0 = make_uint2(Vj.x, Vj.y);
                    uint2 v1 = make_uint2(Vj.z, Vj.w);
                    mma_f16(O[0][2 * j],     pa[0], v0);
                    mma_f16(O[1][2 * j],     pa[1], v0);
                    mma_f16(O[0][2 * j + 1], pa[0], v1);
                    mma_f16(O[1][2 * j + 1], pa[1], v1);
                }
                mma_f16(O[0][8], pa[0], vones);
                mma_f16(O[1][8], pa[1], vones);
            }
        }
    }

    // ---- finalize: l lives in O[t][8][2h] at quad-lane 0 ----
    int q0 = blockIdx.x * QBLK + w * 32 + (lane >> 2);
#pragma unroll
    for (int t = 0; t < 2; t++)
#pragma unroll
        for (int h = 0; h < 2; h++) {
            float l = __shfl_sync(0xffffffffu, O[t][8][2 * h], lane & 28);
            float iv = 1.0f / l;
            int q = q0 + t * 16 + h * 8;
            float* op = g_o + ((size_t)b * NN + q) * 64 + (lane & 3) * 2;
#pragma unroll
            for (int db = 0; db < 8; db++) {
                float2 v = make_float2(O[t][db][2 * h] * iv, O[t][db][2 * h + 1] * iv);
                *(float2*)(op + db * 8) = v;
            }
        }
}

// ---------------------------------------------------------------------------
// Kernel 4: output 1x1 conv + residual, weights staged in smem.
// ---------------------------------------------------------------------------
__global__ __launch_bounds__(256) void out_kernel(
    const float* __restrict__ x,
    const float* __restrict__ wo, const float* __restrict__ bo,
    float* __restrict__ out)
{
    __shared__ float osh[64 * 65];
    __shared__ float wsh[64 * 64];

    int tile = blockIdx.x;
    int b    = tile / (NN / 64);
    int n0   = (tile % (NN / 64)) * 64;
    int tid  = threadIdx.x;
    int p    = tid & 63;
    int cg   = tid >> 6;

    for (int idx = tid; idx < 64 * 64; idx += 256) {
        wsh[idx] = wo[idx];
        int pp = idx >> 6, oo = idx & 63;
        osh[pp * 65 + oo] = g_o[((size_t)b * NN + n0 + pp) * 64 + oo];
    }
    __syncthreads();

    float acc[16];
#pragma unroll
    for (int i = 0; i < 16; i++) acc[i] = bo[cg * 16 + i];

    for (int c4 = 0; c4 < 64; c4 += 4) {
        float o0 = osh[p * 65 + c4 + 0];
        float o1 = osh[p * 65 + c4 + 1];
        float o2 = osh[p * 65 + c4 + 2];
        float o3 = osh[p * 65 + c4 + 3];
#pragma unroll
        for (int i = 0; i < 16; i++) {
            int co = cg * 16 + i;
            float4 w = *(const float4*)(wsh + co * 64 + c4);
            acc[i] += w.x * o0 + w.y * o1 + w.z * o2 + w.w * o3;
        }
    }
#pragma unroll
    for (int i = 0; i < 16; i++) {
        int co = cg * 16 + i;
        size_t oidx = ((size_t)b * CC + co) * NN + n0 + p;
        out[oidx] = x[oidx] + acc[i];
    }
}

// ---------------------------------------------------------------------------
extern "C" void kernel_launch(void* const* d_in, const int* in_sizes, int n_in,
                              void* d_out, int out_size)
{
    const float* x  = (const float*)d_in[0];
    const float* wq = (const float*)d_in[1];
    const float* bq = (const float*)d_in[2];
    const float* wk = (const float*)d_in[3];
    const float* bk = (const float*)d_in[4];
    const float* wv = (const float*)d_in[5];
    const float* bv = (const float*)d_in[6];
    const float* wo = (const float*)d_in[7];
    const float* bo = (const float*)d_in[8];
    float* out = (float*)d_out;

    static bool attr_set = false;
    if (!attr_set) {
        cudaFuncSetAttribute(attn_kernel,
                             cudaFuncAttributeMaxDynamicSharedMemorySize, 65536);
        cudaFuncSetAttribute(qkv_kernel,
                             cudaFuncAttributeMaxDynamicSharedMemorySize, QKV_SMEM);
        attr_set = true;
    }

    stats_kernel<<<BB * CC, 256>>>(x);
    qkv_kernel<<<BB * (NN / 64), 256, QKV_SMEM>>>(x, wq, bq, wk, bk, wv, bv);
    attn_kernel<<<dim3(NN / QBLK, BB), 128, 65536>>>();
    out_kernel<<<BB * (NN / 64), 256>>>(x, wo, bo, out);
}

// round 7
// speedup vs baseline: 13.0832x; 1.0557x over previous
#include <cuda_runtime.h>
#include <cuda_fp16.h>
#include <cuda_bf16.h>
#include <math.h>

#define BB 4
#define CC 64
#define NN 9216       // 96*96
#define NT (NN/64)    // 144 64-key packing tiles
#define QBLK 128      // queries per attention block (4 warps x 32)
#define NRND (NN/128) // 72 staging rounds of 128 keys

// Scratch (static device arrays; no allocation allowed)
__device__ float g_stats[BB * CC * 2];           // mean, rstd per (b,c)
__device__ float g_q[(size_t)BB * NN * CC / 2];  // fp16 A-frag packed (m16n8k16)
__device__ float g_k[(size_t)BB * NN * CC / 2];  // fp16 B-frag packed (uint4 groups)
__device__ float g_v[(size_t)BB * NN * CC / 2];  // fp16 B-frag packed (uint4 groups)
__device__ unsigned g_o[(size_t)BB * NN * 32];   // attention out fp16x2 [b][q][d/2]

// ---------------------------------------------------------------------------
// helpers
// ---------------------------------------------------------------------------
static __device__ __forceinline__ unsigned smem_u32(const void* p) {
    return (unsigned)__cvta_generic_to_shared(p);
}
static __device__ __forceinline__ void cp_async16(unsigned dst, const void* src) {
    asm volatile("cp.async.cg.shared.global [%0], [%1], 16;" :: "r"(dst), "l"(src) : "memory");
}
static __device__ __forceinline__ void cp_commit() {
    asm volatile("cp.async.commit_group;" ::: "memory");
}
static __device__ __forceinline__ unsigned pack_h2(float a, float b) {
    __half2 h = __floats2half2_rn(a, b);
    return *reinterpret_cast<unsigned*>(&h);
}
static __device__ __forceinline__ unsigned ex2_h2(unsigned h) {
    unsigned r;
    asm("ex2.approx.f16x2 %0, %1;" : "=r"(r) : "r"(h));
    return r;
}
static __device__ __forceinline__ unsigned hmax2_u(unsigned a, unsigned b) {
    unsigned r;
    asm("max.f16x2 %0, %1, %2;" : "=r"(r) : "r"(a), "r"(b));
    return r;
}
static __device__ __forceinline__ unsigned hsub2_u(unsigned a, unsigned b) {
    unsigned r;
    asm("sub.f16x2 %0, %1, %2;" : "=r"(r) : "r"(a), "r"(b));
    return r;
}
static __device__ __forceinline__ void mma_f16(float* d, const unsigned* a, uint2 b) {
    asm volatile(
        "mma.sync.aligned.m16n8k16.row.col.f32.f16.f16.f32 "
        "{%0,%1,%2,%3},{%4,%5,%6,%7},{%8,%9},{%0,%1,%2,%3};"
        : "+f"(d[0]), "+f"(d[1]), "+f"(d[2]), "+f"(d[3])
        : "r"(a[0]), "r"(a[1]), "r"(a[2]), "r"(a[3]),
          "r"(b.x), "r"(b.y));
}

// ---------------------------------------------------------------------------
// Kernel 1: instance-norm statistics only. One block per (b,c).
// ---------------------------------------------------------------------------
__global__ __launch_bounds__(256) void stats_kernel(const float* __restrict__ x) {
    int bc = blockIdx.x;
    const float4* xp = (const float4*)(x + (size_t)bc * NN);
    int tid = threadIdx.x;

    float s = 0.f, ss = 0.f;
    for (int i = tid; i < NN / 4; i += 256) {
        float4 v = xp[i];
        s  += v.x + v.y + v.z + v.w;
        ss += v.x * v.x + v.y * v.y + v.z * v.z + v.w * v.w;
    }
    __shared__ float rs[256], rss[256];
    rs[tid] = s; rss[tid] = ss;
    __syncthreads();
    for (int off = 128; off > 0; off >>= 1) {
        if (tid < off) { rs[tid] += rs[tid + off]; rss[tid] += rss[tid + off]; }
        __syncthreads();
    }
    if (tid == 0) {
        float mean = rs[0] * (1.0f / NN);
        float var  = rss[0] * (1.0f / NN) - mean * mean;
        g_stats[bc * 2]     = mean;
        g_stats[bc * 2 + 1] = rsqrtf(var + 1e-5f);
    }
}

// ---------------------------------------------------------------------------
// Kernel 2: fused norm + Q/K/V 1x1 convs via fp16 tensor cores + frag packing.
// ---------------------------------------------------------------------------
#define QS_OUTS 0
#define QS_HSH  16640
#define QS_WSH  25856
#define QS_MEAN 53504
#define QS_RSTD 53760
#define QKV_SMEM 54016

__global__ __launch_bounds__(256) void qkv_kernel(
    const float* __restrict__ x,
    const float* __restrict__ wq, const float* __restrict__ bq,
    const float* __restrict__ wk, const float* __restrict__ bk,
    const float* __restrict__ wv, const float* __restrict__ bv)
{
    extern __shared__ char smem[];
    float*    outs  = (float*)(smem + QS_OUTS);
    unsigned* hsh   = (unsigned*)(smem + QS_HSH);
    unsigned* wsh   = (unsigned*)(smem + QS_WSH);
    float*    smean = (float*)(smem + QS_MEAN);
    float*    srstd = (float*)(smem + QS_RSTD);

    int tile = blockIdx.x;
    int b    = tile / (NN / 64);
    int n0   = (tile % (NN / 64)) * 64;
    int tid  = threadIdx.x;
    int w    = tid >> 5;
    int lane = tid & 31;
    int rp   = lane >> 2;
    int m    = lane & 3;
    int otile = w & 3;
    int nbb   = (w >> 2) * 4;

    if (tid < 64) {
        smean[tid] = g_stats[(b * 64 + tid) * 2];
        srstd[tid] = g_stats[(b * 64 + tid) * 2 + 1];
    }
    __syncthreads();

    for (int idx = tid; idx < 2048; idx += 256) {
        int cp = idx >> 6, p = idx & 63;
        float v0 = (x[((size_t)b * CC + 2 * cp)     * NN + n0 + p] - smean[2 * cp])     * srstd[2 * cp];
        float v1 = (x[((size_t)b * CC + 2 * cp + 1) * NN + n0 + p] - smean[2 * cp + 1]) * srstd[2 * cp + 1];
        hsh[p * 36 + cp] = pack_h2(v0, v1);
    }
    for (int idx = tid; idx < 6144; idx += 256) {
        int mat = idx >> 11;
        int rem = idx & 2047;
        int o = rem >> 5, cp = rem & 31;
        const float* wsrc = (mat == 0) ? wq : (mat == 1) ? wk : wv;
        float2 wv2 = *(const float2*)(wsrc + o * 64 + 2 * cp);
        wsh[mat * 2304 + o * 36 + cp] = pack_h2(wv2.x, wv2.y);
    }
    __syncthreads();

    const float QSCALE = 0.125f * 1.4426950408889634f;  // C^-0.5 * log2(e)
    size_t qbase = ((size_t)b * (NN / 16) + n0 / 16) * 512;
    size_t kvtile = ((size_t)b * NT + n0 / 64) * 2048;

#pragma unroll
    for (int mat = 0; mat < 3; mat++) {
        float acc[4][4];
#pragma unroll
        for (int nb = 0; nb < 4; nb++) {
            acc[nb][0] = 0.f; acc[nb][1] = 0.f; acc[nb][2] = 0.f; acc[nb][3] = 0.f;
        }
        const unsigned* wm = wsh + mat * 2304;
#pragma unroll
        for (int k = 0; k < 4; k++) {
            unsigned a[4];
            int abase = (otile * 16 + rp) * 36 + k * 8 + m;
            a[0] = wm[abase];
            a[1] = wm[abase + 8 * 36];
            a[2] = wm[abase + 4];
            a[3] = wm[abase + 8 * 36 + 4];
#pragma unroll
            for (int nb = 0; nb < 4; nb++) {
                int p = (nbb + nb) * 8 + rp;
                unsigned b0 = hsh[p * 36 + k * 8 + m];
                unsigned b1 = hsh[p * 36 + k * 8 + m + 4];
                mma_f16(acc[nb], a, make_uint2(b0, b1));
            }
        }

        __syncthreads();
        const float* bias = (mat == 0) ? bq : (mat == 1) ? bk : bv;
        float scale = (mat == 0) ? QSCALE : 1.0f;
        float b0v = bias[otile * 16 + rp];
        float b1v = bias[otile * 16 + rp + 8];
        int o0 = otile * 16 + rp;
#pragma unroll
        for (int nb = 0; nb < 4; nb++) {
            int p0 = (nbb + nb) * 8 + 2 * m;
            outs[p0 * 65 + o0]           = (acc[nb][0] + b0v) * scale;
            outs[(p0 + 1) * 65 + o0]     = (acc[nb][1] + b0v) * scale;
            outs[p0 * 65 + o0 + 8]       = (acc[nb][2] + b1v) * scale;
            outs[(p0 + 1) * 65 + o0 + 8] = (acc[nb][3] + b1v) * scale;
        }
        __syncthreads();

        if (mat == 0) {
            unsigned* qdst = (unsigned*)g_q + qbase;
            for (int idx = tid; idx < 2048; idx += 256) {
                int qb = idx >> 9;
                int ks = (idx >> 7) & 3;
                int ln = (idx >> 2) & 31;
                int rg = idx & 3;
                int row = qb * 16 + (ln >> 2) + ((rg & 1) << 3);
                int c0  = ks * 16 + 2 * (ln & 3) + ((rg & 2) << 2);
                qdst[idx] = pack_h2(outs[row * 65 + c0], outs[row * 65 + c0 + 1]);
            }
        } else if (mat == 1) {
            unsigned* kdst = (unsigned*)g_k + kvtile;
            for (int idx = tid; idx < 2048; idx += 256) {
                int nb   = idx >> 8;
                int pair = (idx >> 7) & 1;
                int ln   = (idx >> 2) & 31;
                int q2   = idx & 3;
                int ks = pair * 2 + (q2 >> 1);
                int rg = q2 & 1;
                int key = nb * 8 + (ln >> 2);
                int kr  = ks * 16 + 2 * (ln & 3) + rg * 8;
                kdst[idx] = pack_h2(outs[key * 65 + kr], outs[key * 65 + kr + 1]);
            }
        } else {
            unsigned* vdst = (unsigned*)g_v + kvtile;
            for (int idx = tid; idx < 2048; idx += 256) {
                int kb = idx >> 9;
                int j  = (idx >> 7) & 3;
                int ln = (idx >> 2) & 31;
                int q2 = idx & 3;
                int db = 2 * j + (q2 >> 1);
                int rg = q2 & 1;
                int key0 = kb * 16 + ((ln & 3) << 1) + (rg << 3);
                int d    = db * 8 + (ln >> 2);
                vdst[idx] = pack_h2(outs[key0 * 65 + d], outs[(key0 + 1) * 65 + d]);
            }
        }
    }
}

// ---------------------------------------------------------------------------
// Kernel 3: tensor-core flash attention, fp16 mma.
// S accumulator initialized to -m (scores arrive pre-shifted); fp16 max tree;
// lazy rescale. 128 threads, 2 CTAs/SM, double-buffered 128-key rounds.
// ---------------------------------------------------------------------------
__global__ void __launch_bounds__(128, 2) attn_kernel() {
    extern __shared__ uint4 KV[];   // [2][2048]

    int b    = blockIdx.y;
    int w    = threadIdx.x >> 5;
    int lane = threadIdx.x & 31;

    // ---- Q fragments (registers for whole kernel) ----
    unsigned qa[2][4][4];
    {
        const uint4* qbase = (const uint4*)g_q + ((size_t)b * (NN / 16)) * 128;
        int qblk0 = blockIdx.x * 8 + w * 2;
#pragma unroll
        for (int t = 0; t < 2; t++)
#pragma unroll
            for (int ks = 0; ks < 4; ks++) {
                uint4 v = qbase[((qblk0 + t) * 4 + ks) * 32 + lane];
                qa[t][ks][0] = v.x; qa[t][ks][1] = v.y;
                qa[t][ks][2] = v.z; qa[t][ks][3] = v.w;
            }
    }

    float O[2][9][4];       // db 0..7 = output dims, db 8 = l (ones column)
    float S[2][8][4];
    unsigned P[2][8][2];
    float mrow[2][2];       // running max (log2 domain); init 0 (see theory)
#pragma unroll
    for (int t = 0; t < 2; t++) {
#pragma unroll
        for (int db = 0; db < 9; db++) {
            O[t][db][0] = 0.f; O[t][db][1] = 0.f; O[t][db][2] = 0.f; O[t][db][3] = 0.f;
        }
        mrow[t][0] = 0.f; mrow[t][1] = 0.f;
    }

    unsigned ones = ((lane >> 2) == 0) ? 0x3C003C00u : 0u;
    uint2 vones = make_uint2(ones, ones);

    const uint4* ksrc = (const uint4*)g_k + (size_t)b * NT * 512;
    const uint4* vsrc = (const uint4*)g_v + (size_t)b * NT * 512;

    {
        unsigned sb = smem_u32(&KV[0]);
        for (int i = threadIdx.x; i < 2048; i += 128) {
            const uint4* src = (i < 1024) ? (ksrc + i) : (vsrc + (i - 1024));
            cp_async16(sb + i * 16, src);
        }
        cp_commit();
    }

    for (int rd = 0; rd < NRND; rd++) {
        int buf = rd & 1;
        asm volatile("cp.async.wait_group 0;" ::: "memory");
        __syncthreads();

        if (rd + 1 < NRND) {
            unsigned sb = smem_u32(&KV[(buf ^ 1) * 2048]);
            const uint4* kb = ksrc + (size_t)(rd + 1) * 1024;
            const uint4* vb = vsrc + (size_t)(rd + 1) * 1024;
            for (int i = threadIdx.x; i < 2048; i += 128) {
                const uint4* src = (i < 1024) ? (kb + i) : (vb + (i - 1024));
                cp_async16(sb + i * 16, src);
            }
            cp_commit();
        }

#pragma unroll
        for (int st = 0; st < 2; st++) {
            const uint4* Kf4 = &KV[(size_t)buf * 2048]        + st * 512;
            const uint4* Vf4 = &KV[(size_t)buf * 2048 + 1024] + st * 512;

            // S = Q*K^T - m  (accumulator pre-loaded with -m)
            float negm[2][2] = {{-mrow[0][0], -mrow[0][1]}, {-mrow[1][0], -mrow[1][1]}};
#pragma unroll
            for (int nb = 0; nb < 8; nb++) {
                uint4 A = Kf4[(nb * 2 + 0) * 32 + lane];
                uint4 Bv = Kf4[(nb * 2 + 1) * 32 + lane];
                uint2 kf[4];
                kf[0] = make_uint2(A.x, A.y);
                kf[1] = make_uint2(A.z, A.w);
                kf[2] = make_uint2(Bv.x, Bv.y);
                kf[3] = make_uint2(Bv.z, Bv.w);
#pragma unroll
                for (int t = 0; t < 2; t++) {
                    S[t][nb][0] = negm[t][0]; S[t][nb][1] = negm[t][0];
                    S[t][nb][2] = negm[t][1]; S[t][nb][3] = negm[t][1];
#pragma unroll
                    for (int ks = 0; ks < 4; ks++) mma_f16(S[t][nb], qa[t][ks], kf[ks]);
                }
            }

            // softmax: pack to f16 pairs, fp16 max tree, lazy rescale
#pragma unroll
            for (int t = 0; t < 2; t++)
#pragma unroll
                for (int h = 0; h < 2; h++) {
                    unsigned ph[8];
#pragma unroll
                    for (int nb = 0; nb < 8; nb++)
                        ph[nb] = pack_h2(S[t][nb][2 * h], S[t][nb][2 * h + 1]);
                    unsigned t0 = hmax2_u(ph[0], ph[1]);
                    unsigned t1 = hmax2_u(ph[2], ph[3]);
                    unsigned t2 = hmax2_u(ph[4], ph[5]);
                    unsigned t3 = hmax2_u(ph[6], ph[7]);
                    unsigned hm = hmax2_u(hmax2_u(t0, t1), hmax2_u(t2, t3));
                    hm = hmax2_u(hm, __shfl_xor_sync(0xffffffffu, hm, 1));
                    hm = hmax2_u(hm, __shfl_xor_sync(0xffffffffu, hm, 2));
                    __half2 hh = *reinterpret_cast<__half2*>(&hm);
                    float mxf = fmaxf(__low2float(hh), __high2float(hh));
                    if (__any_sync(0xffffffffu, mxf > 0.f)) {
                        mxf = fmaxf(mxf, 0.f);       // rows w/o update: 0 => exact no-op
                        mrow[t][h] += mxf;
                        float corr = exp2f(-mxf);
#pragma unroll
                        for (int db = 0; db < 9; db++) {
                            O[t][db][2 * h]     *= corr;
                            O[t][db][2 * h + 1] *= corr;
                        }
                        unsigned mx2 = pack_h2(mxf, mxf);
#pragma unroll
                        for (int nb = 0; nb < 8; nb++) ph[nb] = hsub2_u(ph[nb], mx2);
                    }
#pragma unroll
                    for (int nb = 0; nb < 8; nb++) P[t][nb][h] = ex2_h2(ph[nb]);
                }

            // O += P * V (fp16), l via ones column
#pragma unroll
            for (int ks = 0; ks < 4; ks++) {
                unsigned pa[2][4];
#pragma unroll
                for (int t = 0; t < 2; t++) {
                    pa[t][0] = P[t][2 * ks][0];
                    pa[t][1] = P[t][2 * ks][1];
                    pa[t][2] = P[t][2 * ks + 1][0];
                    pa[t][3] = P[t][2 * ks + 1][1];
                }
#pragma unroll
                for (int j = 0; j < 4; j++) {
                    uint4 Vj = Vf4[(ks * 4 + j) * 32 + lane];
                    uint2 v0 = make_uint2(Vj.x, Vj.y);
                    uint2 v1 = make_uint2(Vj.z, Vj.w);
                    mma_f16(O[0][2 * j],     pa[0], v0);
                    mma_f16(O[1][2 * j],     pa[1], v0);
                    mma_f16(O[0][2 * j + 1], pa[0], v1);
                    mma_f16(O[1][2 * j + 1], pa[1], v1);
                }
                mma_f16(O[0][8], pa[0], vones);
                mma_f16(O[1][8], pa[1], vones);
            }
        }
    }

    // ---- finalize: normalize and store fp16 pairs ----
    int q0 = blockIdx.x * QBLK + w * 32 + (lane >> 2);
#pragma unroll
    for (int t = 0; t < 2; t++)
#pragma unroll
        for (int h = 0; h < 2; h++) {
            float l = __shfl_sync(0xffffffffu, O[t][8][2 * h], lane & 28);
            float iv = 1.0f / l;
            int q = q0 + t * 16 + h * 8;
            unsigned* op = g_o + ((size_t)b * NN + q) * 32 + (lane & 3);
#pragma unroll
            for (int db = 0; db < 8; db++)
                op[db * 4] = pack_h2(O[t][db][2 * h] * iv, O[t][db][2 * h + 1] * iv);
        }
}

// ---------------------------------------------------------------------------
// Kernel 4: output 1x1 conv via fp16 mma + residual.
// ---------------------------------------------------------------------------
__global__ __launch_bounds__(256) void out_kernel(
    const float* __restrict__ x,
    const float* __restrict__ wo, const float* __restrict__ bo,
    float* __restrict__ out)
{
    __shared__ unsigned osh[64 * 33];   // attn out fp16 pairs [p][c/2]
    __shared__ unsigned wsh[64 * 36];   // weights fp16 pairs [o][c/2]
    __shared__ float outs[64 * 65];     // staging [p][o]

    int tile = blockIdx.x;
    int b    = tile / (NN / 64);
    int n0   = (tile % (NN / 64)) * 64;
    int tid  = threadIdx.x;
    int w    = tid >> 5;
    int lane = tid & 31;
    int rp   = lane >> 2;
    int m    = lane & 3;
    int otile = w & 3;
    int nbb   = (w >> 2) * 4;

    // stage weights as fp16 pairs
    for (int idx = tid; idx < 2048; idx += 256) {
        int o = idx >> 5, cp = idx & 31;
        float2 wv2 = *(const float2*)(wo + o * 64 + 2 * cp);
        wsh[o * 36 + cp] = pack_h2(wv2.x, wv2.y);
    }
    // stage attention output (already fp16 pairs, coalesced uint4 reads)
    {
        const uint4* osrc = (const uint4*)(g_o + ((size_t)b * NN + n0) * 32);
        for (int idx = tid; idx < 512; idx += 256) {
            uint4 v = osrc[idx];
            int p = idx >> 3, c4 = idx & 7;
            unsigned* d = &osh[p * 33 + c4 * 4];
            d[0] = v.x; d[1] = v.y; d[2] = v.z; d[3] = v.w;
        }
    }
    __syncthreads();

    float acc[4][4];
#pragma unroll
    for (int nb = 0; nb < 4; nb++) {
        acc[nb][0] = 0.f; acc[nb][1] = 0.f; acc[nb][2] = 0.f; acc[nb][3] = 0.f;
    }
#pragma unroll
    for (int ks = 0; ks < 4; ks++) {
        unsigned a[4];
        int abase = (otile * 16 + rp) * 36 + ks * 8 + m;
        a[0] = wsh[abase];
        a[1] = wsh[abase + 8 * 36];
        a[2] = wsh[abase + 4];
        a[3] = wsh[abase + 8 * 36 + 4];
#pragma unroll
        for (int nb = 0; nb < 4; nb++) {
            int p = (nbb + nb) * 8 + rp;
            unsigned b0 = osh[p * 33 + ks * 8 + m];
            unsigned b1 = osh[p * 33 + ks * 8 + m + 4];
            mma_f16(acc[nb], a, make_uint2(b0, b1));
        }
    }

    float b0v = bo[otile * 16 + rp];
    float b1v = bo[otile * 16 + rp + 8];
    int o0 = otile * 16 + rp;
#pragma unroll
    for (int nb = 0; nb < 4; nb++) {
        int p0 = (nbb + nb) * 8 + 2 * m;
        outs[p0 * 65 + o0]           = acc[nb][0] + b0v;
        outs[(p0 + 1) * 65 + o0]     = acc[nb][1] + b0v;
        outs[p0 * 65 + o0 + 8]       = acc[nb][2] + b1v;
        outs[(p0 + 1) * 65 + o0 + 8] = acc[nb][3] + b1v;
    }
    __syncthreads();

    // coalesced residual + store
    int p  = tid & 63;
    int cg = tid >> 6;
#pragma unroll
    for (int i = 0; i < 16; i++) {
        int co = cg * 16 + i;
        size_t oidx = ((size_t)b * CC + co) * NN + n0 + p;
        out[oidx] = x[oidx] + outs[p * 65 + co];
    }
}

// ---------------------------------------------------------------------------
extern "C" void kernel_launch(void* const* d_in, const int* in_sizes, int n_in,
                              void* d_out, int out_size)
{
    const float* x  = (const float*)d_in[0];
    const float* wq = (const float*)d_in[1];
    const float* bq = (const float*)d_in[2];
    const float* wk = (const float*)d_in[3];
    const float* bk = (const float*)d_in[4];
    const float* wv = (const float*)d_in[5];
    const float* bv = (const float*)d_in[6];
    const float* wo = (const float*)d_in[7];
    const float* bo = (const float*)d_in[8];
    float* out = (float*)d_out;

    static bool attr_set = false;
    if (!attr_set) {
        cudaFuncSetAttribute(attn_kernel,
                             cudaFuncAttributeMaxDynamicSharedMemorySize, 65536);
        cudaFuncSetAttribute(qkv_kernel,
                             cudaFuncAttributeMaxDynamicSharedMemorySize, QKV_SMEM);
        attr_set = true;
    }

    stats_kernel<<<BB * CC, 256>>>(x);
    qkv_kernel<<<BB * (NN / 64), 256, QKV_SMEM>>>(x, wq, bq, wk, bk, wv, bv);
    attn_kernel<<<dim3(NN / QBLK, BB), 128, 65536>>>();
    out_kernel<<<BB * (NN / 64), 256>>>(x, wo, bo, out);
}